// round 2
// baseline (speedup 1.0000x reference)
#include <cuda_runtime.h>
#include <math.h>

#define D_MODEL 384
#define N_LAYER 4
#define VOCAB   5000
#define D_INNER 768
#define D_STATE 16
#define DT_RANK 24
#define D_CONV  4
#define BATCH   4
#define SEQ     2048
#define NTOK    (BATCH*SEQ)                 // 8192
#define PROJ_DIM (DT_RANK + 2*D_STATE)      // 56

// ---------------- scratch (device globals; no runtime alloc) ----------------
__device__ float g_resid[NTOK*D_MODEL];
__device__ float g_xnorm[NTOK*D_MODEL];
__device__ float g_xz   [NTOK*2*D_INNER];
__device__ float g_xin  [NTOK*D_INNER];
__device__ float g_proj [NTOK*PROJ_DIM];
__device__ float g_dt   [NTOK*D_INNER];
__device__ float g_y    [NTOK*D_INNER];

// ---------------- embedding gather ----------------
__global__ void embed_kernel(const int* __restrict__ tok,
                             const float* __restrict__ emb,
                             float* __restrict__ out)
{
    int row = blockIdx.x;
    int t = tok[row];
    const float* src = emb + (size_t)t * D_MODEL;
    float* dst = out + (size_t)row * D_MODEL;
    for (int i = threadIdx.x; i < D_MODEL; i += blockDim.x) dst[i] = src[i];
}

// ---------------- rmsnorm (one block of 128 per row of 384) ----------------
__global__ void rmsnorm_kernel(const float* __restrict__ x,
                               const float* __restrict__ w,
                               float* __restrict__ out)
{
    int row = blockIdx.x;
    const float* xr = x + (size_t)row * D_MODEL;
    float v0 = xr[threadIdx.x];
    float v1 = xr[threadIdx.x + 128];
    float v2 = xr[threadIdx.x + 256];
    float s = v0*v0 + v1*v1 + v2*v2;
    #pragma unroll
    for (int o = 16; o; o >>= 1) s += __shfl_xor_sync(0xffffffffu, s, o);
    __shared__ float red[4];
    if ((threadIdx.x & 31) == 0) red[threadIdx.x >> 5] = s;
    __syncthreads();
    s = red[0] + red[1] + red[2] + red[3];
    float sc = rsqrtf(s * (1.0f / D_MODEL) + 1e-5f);
    float* orow = out + (size_t)row * D_MODEL;
    orow[threadIdx.x]       = v0 * sc * w[threadIdx.x];
    orow[threadIdx.x + 128] = v1 * sc * w[threadIdx.x + 128];
    orow[threadIdx.x + 256] = v2 * sc * w[threadIdx.x + 256];
}

// ---------------- causal depthwise conv (k=4) + SiLU ----------------
__global__ void conv_silu_kernel(const float* __restrict__ xz,
                                 const float* __restrict__ cw,
                                 const float* __restrict__ cb,
                                 float* __restrict__ out)
{
    int idx = blockIdx.x * blockDim.x + threadIdx.x;
    if (idx >= NTOK * D_INNER) return;
    int e = idx % D_INNER;
    int l = (idx / D_INNER) % SEQ;
    int b = idx / (D_INNER * SEQ);
    const float* base = xz + (size_t)b * SEQ * (2*D_INNER) + e;
    float acc = cb[e];
    #pragma unroll
    for (int j = 0; j < D_CONV; j++) {
        int lp = l - (D_CONV - 1) + j;
        if (lp >= 0)
            acc = fmaf(cw[e*D_CONV + j], base[(size_t)lp * (2*D_INNER)], acc);
    }
    out[idx] = acc / (1.f + __expf(-acc));   // silu
}

// ---------------- SGEMM 128x128x8, C[M,N] = A[M,K] * B[N,K]^T  ----------------
// epi: 0 = store, 1 = accumulate into C (residual), 2 = softplus(x + bias[n])
__global__ __launch_bounds__(256) void sgemm128(
    const float* __restrict__ A, int lda,
    const float* __restrict__ B, int ldb,
    float* __restrict__ C, int ldc,
    int M, int N, int K,
    const float* __restrict__ bias, int epi)
{
    __shared__ float As[8][128];
    __shared__ float Bs[8][128];
    int bm = blockIdx.y * 128, bn = blockIdx.x * 128;
    int tid = threadIdx.x;
    int tx = tid & 15, ty = tid >> 4;          // 16x16 thread grid, 8x8 microtile
    int lr = tid >> 1;                          // 0..127
    int lc = (tid & 1) * 4;                     // 0 or 4
    const float* Aptr = A + (size_t)(bm + lr) * lda + lc;
    const float* Bptr = B + (size_t)(bn + lr) * ldb + lc;
    bool aval = (bm + lr) < M;
    bool bval = (bn + lr) < N;

    float acc[8][8];
    #pragma unroll
    for (int i = 0; i < 8; i++)
        #pragma unroll
        for (int j = 0; j < 8; j++) acc[i][j] = 0.f;

    for (int k0 = 0; k0 < K; k0 += 8) {
        float4 a4 = aval ? *(const float4*)(Aptr + k0) : make_float4(0,0,0,0);
        float4 b4 = bval ? *(const float4*)(Bptr + k0) : make_float4(0,0,0,0);
        __syncthreads();
        As[lc+0][lr] = a4.x; As[lc+1][lr] = a4.y; As[lc+2][lr] = a4.z; As[lc+3][lr] = a4.w;
        Bs[lc+0][lr] = b4.x; Bs[lc+1][lr] = b4.y; Bs[lc+2][lr] = b4.z; Bs[lc+3][lr] = b4.w;
        __syncthreads();
        #pragma unroll
        for (int kk = 0; kk < 8; kk++) {
            float ar[8], br[8];
            *(float4*)(ar)     = *(const float4*)&As[kk][ty*8];
            *(float4*)(ar + 4) = *(const float4*)&As[kk][ty*8 + 4];
            *(float4*)(br)     = *(const float4*)&Bs[kk][tx*8];
            *(float4*)(br + 4) = *(const float4*)&Bs[kk][tx*8 + 4];
            #pragma unroll
            for (int i = 0; i < 8; i++)
                #pragma unroll
                for (int j = 0; j < 8; j++)
                    acc[i][j] = fmaf(ar[i], br[j], acc[i][j]);
        }
    }

    #pragma unroll
    for (int i = 0; i < 8; i++) {
        int m = bm + ty*8 + i;
        if (m >= M) continue;
        float* crow = C + (size_t)m * ldc;
        #pragma unroll
        for (int j = 0; j < 8; j++) {
            int n = bn + tx*8 + j;
            if (n >= N) continue;
            float v = acc[i][j];
            if (epi == 1) {
                v += crow[n];
            } else if (epi == 2) {
                v += bias[n];
                v = (v > 20.f) ? v : log1pf(__expf(v));   // softplus
            }
            crow[n] = v;
        }
    }
}

// ---------------- SGEMM 64x64x16 (for skinny N=56 x_proj) ----------------
__global__ __launch_bounds__(256) void sgemm64(
    const float* __restrict__ A, int lda,
    const float* __restrict__ B, int ldb,
    float* __restrict__ C, int ldc,
    int M, int N, int K)
{
    __shared__ float As[16][65];
    __shared__ float Bs[16][65];
    int bm = blockIdx.y * 64, bn = blockIdx.x * 64;
    int tid = threadIdx.x;
    int tr = (tid / 16) * 4, tc = (tid % 16) * 4;
    int lr = tid / 4, lc = (tid % 4) * 4;
    float acc[4][4];
    #pragma unroll
    for (int i = 0; i < 4; i++)
        #pragma unroll
        for (int j = 0; j < 4; j++) acc[i][j] = 0.f;

    for (int k0 = 0; k0 < K; k0 += 16) {
        #pragma unroll
        for (int j = 0; j < 4; j++) {
            int kk = k0 + lc + j;
            As[lc+j][lr] = (bm+lr < M && kk < K) ? A[(size_t)(bm+lr)*lda + kk] : 0.f;
            Bs[lc+j][lr] = (bn+lr < N && kk < K) ? B[(size_t)(bn+lr)*ldb + kk] : 0.f;
        }
        __syncthreads();
        #pragma unroll
        for (int kk = 0; kk < 16; kk++) {
            float ar[4], br[4];
            #pragma unroll
            for (int i = 0; i < 4; i++) { ar[i] = As[kk][tr+i]; br[i] = Bs[kk][tc+i]; }
            #pragma unroll
            for (int i = 0; i < 4; i++)
                #pragma unroll
                for (int j = 0; j < 4; j++)
                    acc[i][j] = fmaf(ar[i], br[j], acc[i][j]);
        }
        __syncthreads();
    }
    #pragma unroll
    for (int i = 0; i < 4; i++) {
        int m = bm + tr + i;
        if (m >= M) continue;
        #pragma unroll
        for (int j = 0; j < 4; j++) {
            int n = bn + tc + j;
            if (n < N) C[(size_t)m*ldc + n] = acc[i][j];
        }
    }
}

// ---------------- selective scan: 16 lanes per (b,e), seq over L ----------------
__global__ __launch_bounds__(256) void scan_kernel(
    const float* __restrict__ dt, const float* __restrict__ xin,
    const float* __restrict__ proj, const float* __restrict__ xz,
    const float* __restrict__ A_log, const float* __restrict__ Dp,
    float* __restrict__ y)
{
    int g = blockIdx.x * 16 + (threadIdx.x >> 4);  // group over (b,e)
    int n = threadIdx.x & 15;                      // state index
    int b = g / D_INNER;
    int e = g % D_INNER;
    float a  = -__expf(A_log[e * D_STATE + n]);
    float Dv = Dp[e];
    float h = 0.f;
    const float* dt_p = dt  + (size_t)b * SEQ * D_INNER + e;
    const float* x_p  = xin + (size_t)b * SEQ * D_INNER + e;
    const float* bc_p = proj + (size_t)b * SEQ * PROJ_DIM + DT_RANK + n;
    const float* z_p  = xz  + (size_t)b * SEQ * (2*D_INNER) + D_INNER + e;
    float* y_p        = y   + (size_t)b * SEQ * D_INNER + e;

    for (int l = 0; l < SEQ; l++) {
        float dt_t = dt_p[(size_t)l * D_INNER];
        float x_t  = x_p [(size_t)l * D_INNER];
        float Bt   = bc_p[(size_t)l * PROJ_DIM];
        float Ct   = bc_p[(size_t)l * PROJ_DIM + D_STATE];
        h = h * __expf(dt_t * a) + dt_t * x_t * Bt;
        float yv = h * Ct;
        yv += __shfl_xor_sync(0xffffffffu, yv, 8);
        yv += __shfl_xor_sync(0xffffffffu, yv, 4);
        yv += __shfl_xor_sync(0xffffffffu, yv, 2);
        yv += __shfl_xor_sync(0xffffffffu, yv, 1);
        if (n == 0) {
            float z  = z_p[(size_t)l * (2*D_INNER)];
            float sz = z / (1.f + __expf(-z));          // silu(z)
            y_p[(size_t)l * D_INNER] = (yv + Dv * x_t) * sz;
        }
    }
}

// ---------------- launcher ----------------
extern "C" void kernel_launch(void* const* d_in, const int* in_sizes, int n_in,
                              void* d_out, int out_size)
{
    const int*   tokens = (const int*)  d_in[0];
    const float* embed  = (const float*)d_in[1];
    const float* norm_w = (const float*)d_in[2];
    const float* in_w   = (const float*)d_in[3];
    const float* conv_w = (const float*)d_in[4];
    const float* conv_b = (const float*)d_in[5];
    const float* xp_w   = (const float*)d_in[6];
    const float* dt_w   = (const float*)d_in[7];
    const float* dt_b   = (const float*)d_in[8];
    const float* A_log  = (const float*)d_in[9];
    const float* Dp     = (const float*)d_in[10];
    const float* out_w  = (const float*)d_in[11];
    const float* fnorm  = (const float*)d_in[12];
    float* out = (float*)d_out;

    float *resid, *xnorm, *xz, *xin, *proj, *dtb, *yb;
    cudaGetSymbolAddress((void**)&resid, g_resid);
    cudaGetSymbolAddress((void**)&xnorm, g_xnorm);
    cudaGetSymbolAddress((void**)&xz,    g_xz);
    cudaGetSymbolAddress((void**)&xin,   g_xin);
    cudaGetSymbolAddress((void**)&proj,  g_proj);
    cudaGetSymbolAddress((void**)&dtb,   g_dt);
    cudaGetSymbolAddress((void**)&yb,    g_y);

    embed_kernel<<<NTOK, 128>>>(tokens, embed, resid);

    for (int i = 0; i < N_LAYER; i++) {
        rmsnorm_kernel<<<NTOK, 128>>>(resid, norm_w + (size_t)i * D_MODEL, xnorm);

        // xz = xnorm @ in_proj^T   (8192 x 1536 x 384)
        dim3 g1((2*D_INNER)/128, NTOK/128);
        sgemm128<<<g1, 256>>>(xnorm, D_MODEL,
                              in_w + (size_t)i * 2*D_INNER*D_MODEL, D_MODEL,
                              xz, 2*D_INNER, NTOK, 2*D_INNER, D_MODEL, nullptr, 0);

        // conv + silu -> xin
        conv_silu_kernel<<<(NTOK*D_INNER + 255)/256, 256>>>(
            xz, conv_w + (size_t)i * D_INNER*D_CONV, conv_b + (size_t)i * D_INNER, xin);

        // proj = xin @ x_proj^T    (8192 x 56 x 768)
        dim3 g2(1, NTOK/64);
        sgemm64<<<g2, 256>>>(xin, D_INNER,
                             xp_w + (size_t)i * PROJ_DIM*D_INNER, D_INNER,
                             proj, PROJ_DIM, NTOK, PROJ_DIM, D_INNER);

        // dt = softplus(proj[:, :24] @ dt_w^T + dt_b)   (8192 x 768 x 24)
        dim3 g3(D_INNER/128, NTOK/128);
        sgemm128<<<g3, 256>>>(proj, PROJ_DIM,
                              dt_w + (size_t)i * D_INNER*DT_RANK, DT_RANK,
                              dtb, D_INNER, NTOK, D_INNER, DT_RANK,
                              dt_b + (size_t)i * D_INNER, 2);

        // selective scan + D skip + silu(z) gate -> yb
        scan_kernel<<<(BATCH*D_INNER)/16, 256>>>(
            dtb, xin, proj, xz,
            A_log + (size_t)i * D_INNER*D_STATE, Dp + (size_t)i * D_INNER, yb);

        // resid += yb @ out_proj^T  (8192 x 384 x 768)
        dim3 g4(D_MODEL/128, NTOK/128);
        sgemm128<<<g4, 256>>>(yb, D_INNER,
                              out_w + (size_t)i * D_MODEL*D_INNER, D_INNER,
                              resid, D_MODEL, NTOK, D_MODEL, D_INNER, nullptr, 1);
    }

    rmsnorm_kernel<<<NTOK, 128>>>(resid, fnorm, xnorm);

    // logits = xnorm @ embed^T   (8192 x 5000 x 384)
    dim3 g5((VOCAB + 127)/128, NTOK/128);
    sgemm128<<<g5, 256>>>(xnorm, D_MODEL, embed, D_MODEL,
                          out, VOCAB, NTOK, VOCAB, D_MODEL, nullptr, 0);
}

// round 4
// speedup vs baseline: 1.8679x; 1.8679x over previous
#include <cuda_runtime.h>
#include <math.h>

#define D_MODEL 384
#define N_LAYER 4
#define VOCAB   5000
#define D_INNER 768
#define D_STATE 16
#define DT_RANK 24
#define D_CONV  4
#define BATCH   4
#define SEQ     2048
#define NTOK    (BATCH*SEQ)                 // 8192
#define PROJ_DIM (DT_RANK + 2*D_STATE)      // 56

// ---------------- scratch (device globals; no runtime alloc) ----------------
__device__ float g_resid[NTOK*D_MODEL];
__device__ float g_xnorm[NTOK*D_MODEL];
__device__ float g_xz   [NTOK*2*D_INNER];
__device__ float g_xin  [NTOK*D_INNER];
__device__ float g_proj [NTOK*PROJ_DIM];
__device__ float g_dt   [NTOK*D_INNER];
__device__ float g_y    [NTOK*D_INNER];

// ---------------- embedding gather ----------------
__global__ void embed_kernel(const int* __restrict__ tok,
                             const float* __restrict__ emb,
                             float* __restrict__ out)
{
    int row = blockIdx.x;
    int t = tok[row];
    const float* src = emb + (size_t)t * D_MODEL;
    float* dst = out + (size_t)row * D_MODEL;
    for (int i = threadIdx.x; i < D_MODEL; i += blockDim.x) dst[i] = src[i];
}

// ---------------- rmsnorm (one block of 128 per row of 384) ----------------
__global__ void rmsnorm_kernel(const float* __restrict__ x,
                               const float* __restrict__ w,
                               float* __restrict__ out)
{
    int row = blockIdx.x;
    const float* xr = x + (size_t)row * D_MODEL;
    float v0 = xr[threadIdx.x];
    float v1 = xr[threadIdx.x + 128];
    float v2 = xr[threadIdx.x + 256];
    float s = v0*v0 + v1*v1 + v2*v2;
    #pragma unroll
    for (int o = 16; o; o >>= 1) s += __shfl_xor_sync(0xffffffffu, s, o);
    __shared__ float red[4];
    if ((threadIdx.x & 31) == 0) red[threadIdx.x >> 5] = s;
    __syncthreads();
    s = red[0] + red[1] + red[2] + red[3];
    float sc = rsqrtf(s * (1.0f / D_MODEL) + 1e-5f);
    float* orow = out + (size_t)row * D_MODEL;
    orow[threadIdx.x]       = v0 * sc * w[threadIdx.x];
    orow[threadIdx.x + 128] = v1 * sc * w[threadIdx.x + 128];
    orow[threadIdx.x + 256] = v2 * sc * w[threadIdx.x + 256];
}

// ---------------- causal depthwise conv (k=4) + SiLU ----------------
__global__ void conv_silu_kernel(const float* __restrict__ xz,
                                 const float* __restrict__ cw,
                                 const float* __restrict__ cb,
                                 float* __restrict__ out)
{
    int idx = blockIdx.x * blockDim.x + threadIdx.x;
    if (idx >= NTOK * D_INNER) return;
    int e = idx % D_INNER;
    int l = (idx / D_INNER) % SEQ;
    int b = idx / (D_INNER * SEQ);
    const float* base = xz + (size_t)b * SEQ * (2*D_INNER) + e;
    float acc = cb[e];
    #pragma unroll
    for (int j = 0; j < D_CONV; j++) {
        int lp = l - (D_CONV - 1) + j;
        if (lp >= 0)
            acc = fmaf(cw[e*D_CONV + j], base[(size_t)lp * (2*D_INNER)], acc);
    }
    out[idx] = acc / (1.f + __expf(-acc));   // silu
}

// ---------------- SGEMM 128x128x16, double-buffered, C = A * B^T ----------------
// EPI: 0 = store, 1 = accumulate into C (residual), 2 = softplus(x + bias[n])
// FULLK: K is a multiple of 16 and rows are 16B-aligned -> float4 global loads.
template<int EPI, bool FULLK>
__global__ __launch_bounds__(256, 2) void sgemm128(
    const float* __restrict__ A, int lda,
    const float* __restrict__ B, int ldb,
    float* __restrict__ C, int ldc,
    int M, int N, int K,
    const float* __restrict__ bias)
{
    __shared__ float As[2][16][128];
    __shared__ float Bs[2][16][128];
    int bm = blockIdx.y * 128, bn = blockIdx.x * 128;
    int tid = threadIdx.x;
    int tx = tid & 15, ty = tid >> 4;       // 16x16 thread grid, 8x8 microtile
    int lr = tid >> 1;                       // 0..127 (tile row)
    int lc = (tid & 1) * 8;                  // 0 or 8 (k offset)
    const float* Aptr = A + (size_t)(bm + lr) * lda + lc;
    const float* Bptr = B + (size_t)(bn + lr) * ldb + lc;
    bool aval = (bm + lr) < M;
    bool bval = (bn + lr) < N;
    int ntiles = (K + 15) / 16;

    float acc[8][8];
    #pragma unroll
    for (int i = 0; i < 8; i++)
        #pragma unroll
        for (int j = 0; j < 8; j++) acc[i][j] = 0.f;

    float ra[8], rb[8];
    #pragma unroll
    for (int j = 0; j < 8; j++) { ra[j] = 0.f; rb[j] = 0.f; }

    // prologue: load tile 0 into regs
    if (FULLK) {
        if (aval) { *(float4*)ra = *(const float4*)(Aptr); *(float4*)(ra+4) = *(const float4*)(Aptr+4); }
        if (bval) { *(float4*)rb = *(const float4*)(Bptr); *(float4*)(rb+4) = *(const float4*)(Bptr+4); }
    } else {
        #pragma unroll
        for (int j = 0; j < 8; j++) {
            if (aval && (lc + j) < K) ra[j] = Aptr[j];
            if (bval && (lc + j) < K) rb[j] = Bptr[j];
        }
    }
    #pragma unroll
    for (int j = 0; j < 8; j++) { As[0][lc+j][lr] = ra[j]; Bs[0][lc+j][lr] = rb[j]; }
    __syncthreads();

    for (int t = 0; t < ntiles; t++) {
        int cur = t & 1;
        bool more = (t + 1) < ntiles;
        if (more) {
            int k0 = (t + 1) * 16;
            if (FULLK) {
                if (aval) { *(float4*)ra = *(const float4*)(Aptr+k0); *(float4*)(ra+4) = *(const float4*)(Aptr+k0+4); }
                if (bval) { *(float4*)rb = *(const float4*)(Bptr+k0); *(float4*)(rb+4) = *(const float4*)(Bptr+k0+4); }
            } else {
                #pragma unroll
                for (int j = 0; j < 8; j++) {
                    ra[j] = (aval && (k0 + lc + j) < K) ? Aptr[k0+j] : 0.f;
                    rb[j] = (bval && (k0 + lc + j) < K) ? Bptr[k0+j] : 0.f;
                }
            }
        }
        #pragma unroll
        for (int kk = 0; kk < 16; kk++) {
            float arv[8], brv[8];
            *(float4*)(arv)     = *(const float4*)&As[cur][kk][ty*8];
            *(float4*)(arv + 4) = *(const float4*)&As[cur][kk][ty*8 + 4];
            *(float4*)(brv)     = *(const float4*)&Bs[cur][kk][tx*8];
            *(float4*)(brv + 4) = *(const float4*)&Bs[cur][kk][tx*8 + 4];
            #pragma unroll
            for (int i = 0; i < 8; i++)
                #pragma unroll
                for (int j = 0; j < 8; j++)
                    acc[i][j] = fmaf(arv[i], brv[j], acc[i][j]);
        }
        if (more) {
            #pragma unroll
            for (int j = 0; j < 8; j++) { As[cur^1][lc+j][lr] = ra[j]; Bs[cur^1][lc+j][lr] = rb[j]; }
        }
        __syncthreads();
    }

    #pragma unroll
    for (int i = 0; i < 8; i++) {
        int m = bm + ty*8 + i;
        if (m >= M) continue;
        float* crow = C + (size_t)m * ldc;
        #pragma unroll
        for (int j = 0; j < 8; j++) {
            int n = bn + tx*8 + j;
            if (n >= N) continue;
            float v = acc[i][j];
            if (EPI == 1) {
                v += crow[n];
            } else if (EPI == 2) {
                v += bias[n];
                v = (v > 20.f) ? v : log1pf(__expf(v));   // softplus
            }
            crow[n] = v;
        }
    }
}

// ---------------- SGEMM 64x64x16 (for skinny N=56 x_proj) ----------------
__global__ __launch_bounds__(256) void sgemm64(
    const float* __restrict__ A, int lda,
    const float* __restrict__ B, int ldb,
    float* __restrict__ C, int ldc,
    int M, int N, int K)
{
    __shared__ float As[16][65];
    __shared__ float Bs[16][65];
    int bm = blockIdx.y * 64, bn = blockIdx.x * 64;
    int tid = threadIdx.x;
    int tr = (tid / 16) * 4, tc = (tid % 16) * 4;
    int lr = tid / 4, lc = (tid % 4) * 4;
    float acc[4][4];
    #pragma unroll
    for (int i = 0; i < 4; i++)
        #pragma unroll
        for (int j = 0; j < 4; j++) acc[i][j] = 0.f;

    for (int k0 = 0; k0 < K; k0 += 16) {
        #pragma unroll
        for (int j = 0; j < 4; j++) {
            int kk = k0 + lc + j;
            As[lc+j][lr] = (bm+lr < M && kk < K) ? A[(size_t)(bm+lr)*lda + kk] : 0.f;
            Bs[lc+j][lr] = (bn+lr < N && kk < K) ? B[(size_t)(bn+lr)*ldb + kk] : 0.f;
        }
        __syncthreads();
        #pragma unroll
        for (int kk = 0; kk < 16; kk++) {
            float ar[4], br[4];
            #pragma unroll
            for (int i = 0; i < 4; i++) { ar[i] = As[kk][tr+i]; br[i] = Bs[kk][tc+i]; }
            #pragma unroll
            for (int i = 0; i < 4; i++)
                #pragma unroll
                for (int j = 0; j < 4; j++)
                    acc[i][j] = fmaf(ar[i], br[j], acc[i][j]);
        }
        __syncthreads();
    }
    #pragma unroll
    for (int i = 0; i < 4; i++) {
        int m = bm + tr + i;
        if (m >= M) continue;
        #pragma unroll
        for (int j = 0; j < 4; j++) {
            int n = bn + tc + j;
            if (n < N) C[(size_t)m*ldc + n] = acc[i][j];
        }
    }
}

// ---------------- selective scan: 16 lanes per (b,e), chunked prefetch ----------------
__global__ __launch_bounds__(256) void scan_kernel(
    const float* __restrict__ dt, const float* __restrict__ xin,
    const float* __restrict__ proj, const float* __restrict__ xz,
    const float* __restrict__ A_log, const float* __restrict__ Dp,
    float* __restrict__ y)
{
    int g = blockIdx.x * 16 + (threadIdx.x >> 4);  // group over (b,e)
    int n = threadIdx.x & 15;                      // state index
    int b = g / D_INNER;
    int e = g % D_INNER;
    float a  = -__expf(A_log[e * D_STATE + n]);
    float Dv = Dp[e];
    float h = 0.f;
    const float* dt_p = dt  + (size_t)b * SEQ * D_INNER + e;
    const float* x_p  = xin + (size_t)b * SEQ * D_INNER + e;
    const float* bc_p = proj + (size_t)b * SEQ * PROJ_DIM + DT_RANK + n;
    const float* z_p  = xz  + (size_t)b * SEQ * (2*D_INNER) + D_INNER + e;
    float* y_p        = y   + (size_t)b * SEQ * D_INNER + e;

    // process in chunks of 8: batch all loads (high MLP), then 8 serial steps
    for (int l0 = 0; l0 < SEQ; l0 += 8) {
        float dtv[8], xv[8], Bv[8], Cv[8], zv[8];
        #pragma unroll
        for (int j = 0; j < 8; j++) {
            size_t l = (size_t)(l0 + j);
            dtv[j] = dt_p[l * D_INNER];
            xv[j]  = x_p [l * D_INNER];
            Bv[j]  = bc_p[l * PROJ_DIM];
            Cv[j]  = bc_p[l * PROJ_DIM + D_STATE];
            zv[j]  = z_p [l * (2*D_INNER)];
        }
        #pragma unroll
        for (int j = 0; j < 8; j++) {
            h = h * __expf(dtv[j] * a) + dtv[j] * xv[j] * Bv[j];
            float yv = h * Cv[j];
            yv += __shfl_xor_sync(0xffffffffu, yv, 8);
            yv += __shfl_xor_sync(0xffffffffu, yv, 4);
            yv += __shfl_xor_sync(0xffffffffu, yv, 2);
            yv += __shfl_xor_sync(0xffffffffu, yv, 1);
            if (n == 0) {
                float z  = zv[j];
                float sz = z / (1.f + __expf(-z));          // silu(z)
                y_p[(size_t)(l0 + j) * D_INNER] = (yv + Dv * xv[j]) * sz;
            }
        }
    }
}

// ---------------- launcher ----------------
extern "C" void kernel_launch(void* const* d_in, const int* in_sizes, int n_in,
                              void* d_out, int out_size)
{
    const int*   tokens = (const int*)  d_in[0];
    const float* embed  = (const float*)d_in[1];
    const float* norm_w = (const float*)d_in[2];
    const float* in_w   = (const float*)d_in[3];
    const float* conv_w = (const float*)d_in[4];
    const float* conv_b = (const float*)d_in[5];
    const float* xp_w   = (const float*)d_in[6];
    const float* dt_w   = (const float*)d_in[7];
    const float* dt_b   = (const float*)d_in[8];
    const float* A_log  = (const float*)d_in[9];
    const float* Dp     = (const float*)d_in[10];
    const float* out_w  = (const float*)d_in[11];
    const float* fnorm  = (const float*)d_in[12];
    float* out = (float*)d_out;

    float *resid, *xnorm, *xz, *xin, *proj, *dtb, *yb;
    cudaGetSymbolAddress((void**)&resid, g_resid);
    cudaGetSymbolAddress((void**)&xnorm, g_xnorm);
    cudaGetSymbolAddress((void**)&xz,    g_xz);
    cudaGetSymbolAddress((void**)&xin,   g_xin);
    cudaGetSymbolAddress((void**)&proj,  g_proj);
    cudaGetSymbolAddress((void**)&dtb,   g_dt);
    cudaGetSymbolAddress((void**)&yb,    g_y);

    embed_kernel<<<NTOK, 128>>>(tokens, embed, resid);

    for (int i = 0; i < N_LAYER; i++) {
        rmsnorm_kernel<<<NTOK, 128>>>(resid, norm_w + (size_t)i * D_MODEL, xnorm);

        // xz = xnorm @ in_proj^T   (8192 x 1536 x 384)
        dim3 g1((2*D_INNER)/128, NTOK/128);
        sgemm128<0, true><<<g1, 256>>>(xnorm, D_MODEL,
                              in_w + (size_t)i * 2*D_INNER*D_MODEL, D_MODEL,
                              xz, 2*D_INNER, NTOK, 2*D_INNER, D_MODEL, nullptr);

        // conv + silu -> xin
        conv_silu_kernel<<<(NTOK*D_INNER + 255)/256, 256>>>(
            xz, conv_w + (size_t)i * D_INNER*D_CONV, conv_b + (size_t)i * D_INNER, xin);

        // proj = xin @ x_proj^T    (8192 x 56 x 768)
        dim3 g2(1, NTOK/64);
        sgemm64<<<g2, 256>>>(xin, D_INNER,
                             xp_w + (size_t)i * PROJ_DIM*D_INNER, D_INNER,
                             proj, PROJ_DIM, NTOK, PROJ_DIM, D_INNER);

        // dt = softplus(proj[:, :24] @ dt_w^T + dt_b)   (8192 x 768 x 24)
        dim3 g3(D_INNER/128, NTOK/128);
        sgemm128<2, false><<<g3, 256>>>(proj, PROJ_DIM,
                              dt_w + (size_t)i * D_INNER*DT_RANK, DT_RANK,
                              dtb, D_INNER, NTOK, D_INNER, DT_RANK,
                              dt_b + (size_t)i * D_INNER);

        // selective scan + D skip + silu(z) gate -> yb
        scan_kernel<<<(BATCH*D_INNER)/16, 256>>>(
            dtb, xin, proj, xz,
            A_log + (size_t)i * D_INNER*D_STATE, Dp + (size_t)i * D_INNER, yb);

        // resid += yb @ out_proj^T  (8192 x 384 x 768)
        dim3 g4(D_MODEL/128, NTOK/128);
        sgemm128<1, true><<<g4, 256>>>(yb, D_INNER,
                              out_w + (size_t)i * D_MODEL*D_INNER, D_INNER,
                              resid, D_MODEL, NTOK, D_MODEL, D_INNER, nullptr);
    }

    rmsnorm_kernel<<<NTOK, 128>>>(resid, fnorm, xnorm);

    // logits = xnorm @ embed^T   (8192 x 5000 x 384)
    dim3 g5((VOCAB + 127)/128, NTOK/128);
    sgemm128<0, true><<<g5, 256>>>(xnorm, D_MODEL, embed, D_MODEL,
                          out, VOCAB, NTOK, VOCAB, D_MODEL, nullptr);
}

// round 5
// speedup vs baseline: 2.8138x; 1.5064x over previous
#include <cuda_runtime.h>
#include <math.h>
#include <stdint.h>

#define D_MODEL 384
#define N_LAYER 4
#define VOCAB   5000
#define D_INNER 768
#define D_STATE 16
#define DT_RANK 24
#define D_CONV  4
#define BATCH   4
#define SEQ     2048
#define NTOK    (BATCH*SEQ)                 // 8192
#define PROJ_DIM (DT_RANK + 2*D_STATE)      // 56

// ---------------- scratch (device globals; no runtime alloc) ----------------
__device__ float g_resid[NTOK*D_MODEL];
__device__ float g_xnorm[NTOK*D_MODEL];
__device__ float g_xz   [NTOK*2*D_INNER];
__device__ float g_xin  [NTOK*D_INNER];
__device__ float g_proj [NTOK*PROJ_DIM];
__device__ float g_dt   [NTOK*D_INNER];
__device__ float g_y    [NTOK*D_INNER];

__device__ __forceinline__ uint32_t to_tf32(float x) {
    uint32_t r;
    asm("cvt.rna.tf32.f32 %0, %1;" : "=r"(r) : "f"(x));
    return r;
}

// ---------------- embedding gather ----------------
__global__ void embed_kernel(const int* __restrict__ tok,
                             const float* __restrict__ emb,
                             float* __restrict__ out)
{
    int row = blockIdx.x;
    int t = tok[row];
    const float* src = emb + (size_t)t * D_MODEL;
    float* dst = out + (size_t)row * D_MODEL;
    for (int i = threadIdx.x; i < D_MODEL; i += blockDim.x) dst[i] = src[i];
}

// ---------------- rmsnorm (one block of 128 per row of 384) ----------------
__global__ void rmsnorm_kernel(const float* __restrict__ x,
                               const float* __restrict__ w,
                               float* __restrict__ out)
{
    int row = blockIdx.x;
    const float* xr = x + (size_t)row * D_MODEL;
    float v0 = xr[threadIdx.x];
    float v1 = xr[threadIdx.x + 128];
    float v2 = xr[threadIdx.x + 256];
    float s = v0*v0 + v1*v1 + v2*v2;
    #pragma unroll
    for (int o = 16; o; o >>= 1) s += __shfl_xor_sync(0xffffffffu, s, o);
    __shared__ float red[4];
    if ((threadIdx.x & 31) == 0) red[threadIdx.x >> 5] = s;
    __syncthreads();
    s = red[0] + red[1] + red[2] + red[3];
    float sc = rsqrtf(s * (1.0f / D_MODEL) + 1e-5f);
    float* orow = out + (size_t)row * D_MODEL;
    orow[threadIdx.x]       = v0 * sc * w[threadIdx.x];
    orow[threadIdx.x + 128] = v1 * sc * w[threadIdx.x + 128];
    orow[threadIdx.x + 256] = v2 * sc * w[threadIdx.x + 256];
}

// ---------------- causal depthwise conv (k=4) + SiLU ----------------
__global__ void conv_silu_kernel(const float* __restrict__ xz,
                                 const float* __restrict__ cw,
                                 const float* __restrict__ cb,
                                 float* __restrict__ out)
{
    int idx = blockIdx.x * blockDim.x + threadIdx.x;
    if (idx >= NTOK * D_INNER) return;
    int e = idx % D_INNER;
    int l = (idx / D_INNER) % SEQ;
    int b = idx / (D_INNER * SEQ);
    const float* base = xz + (size_t)b * SEQ * (2*D_INNER) + e;
    float acc = cb[e];
    #pragma unroll
    for (int j = 0; j < D_CONV; j++) {
        int lp = l - (D_CONV - 1) + j;
        if (lp >= 0)
            acc = fmaf(cw[e*D_CONV + j], base[(size_t)lp * (2*D_INNER)], acc);
    }
    out[idx] = acc / (1.f + __expf(-acc));   // silu
}

// ============ TF32 tensor-core GEMM: C[M,N] = A[M,K] * B[N,K]^T ============
// Block 128x128, k-tile 16, double buffered. 8 warps (2m x 4n), warp = 64x32.
// EPI: 0 = store, 1 = accumulate into C, 2 = softplus(x + bias[n])
// FULLK: K multiple of 16 and rows 16B-aligned -> float4 loads.
#define SMP 136   // smem row pitch in words (136 % 32 == 8 -> conflict-free frags)

template<int EPI, bool FULLK>
__global__ __launch_bounds__(256, 2) void tfgemm(
    const float* __restrict__ A, int lda,
    const float* __restrict__ B, int ldb,
    float* __restrict__ C, int ldc,
    int M, int N, int K,
    const float* __restrict__ bias)
{
    __shared__ uint32_t As[2][16][SMP];
    __shared__ uint32_t Bs[2][16][SMP];

    int bm = blockIdx.y * 128, bn = blockIdx.x * 128;
    int tid = threadIdx.x;
    int lane = tid & 31;
    int wid  = tid >> 5;
    int wm = wid >> 2;          // 0..1  (m 64)
    int wn = wid & 3;           // 0..3  (n 32)
    int lq = lane >> 2;         // 0..7  group id
    int lr4 = lane & 3;         // 0..3  thread in group

    // global load mapping: 256 threads load 128 rows x 16 k (8 floats each)
    int glr = tid >> 1;         // 0..127
    int glc = (tid & 1) * 8;    // 0 or 8
    const float* Aptr = A + (size_t)(bm + glr) * lda + glc;
    const float* Bptr = B + (size_t)(bn + glr) * ldb + glc;
    bool aval = (bm + glr) < M;
    bool bval = (bn + glr) < N;
    int ntiles = (K + 15) / 16;

    float acc[4][4][4];
    #pragma unroll
    for (int i = 0; i < 4; i++)
        #pragma unroll
        for (int j = 0; j < 4; j++)
            #pragma unroll
            for (int c = 0; c < 4; c++) acc[i][j][c] = 0.f;

    float ra[8], rb[8];
    #pragma unroll
    for (int j = 0; j < 8; j++) { ra[j] = 0.f; rb[j] = 0.f; }

    // prologue: tile 0
    if (FULLK) {
        if (aval) { *(float4*)ra = *(const float4*)(Aptr); *(float4*)(ra+4) = *(const float4*)(Aptr+4); }
        if (bval) { *(float4*)rb = *(const float4*)(Bptr); *(float4*)(rb+4) = *(const float4*)(Bptr+4); }
    } else {
        #pragma unroll
        for (int j = 0; j < 8; j++) {
            ra[j] = (aval && (glc + j) < K) ? Aptr[j] : 0.f;
            rb[j] = (bval && (glc + j) < K) ? Bptr[j] : 0.f;
        }
    }
    #pragma unroll
    for (int j = 0; j < 8; j++) {
        As[0][glc+j][glr] = to_tf32(ra[j]);
        Bs[0][glc+j][glr] = to_tf32(rb[j]);
    }
    __syncthreads();

    for (int t = 0; t < ntiles; t++) {
        int cur = t & 1;
        bool more = (t + 1) < ntiles;
        if (more) {
            int k0 = (t + 1) * 16;
            if (FULLK) {
                if (aval) { *(float4*)ra = *(const float4*)(Aptr+k0); *(float4*)(ra+4) = *(const float4*)(Aptr+k0+4); }
                if (bval) { *(float4*)rb = *(const float4*)(Bptr+k0); *(float4*)(rb+4) = *(const float4*)(Bptr+k0+4); }
            } else {
                #pragma unroll
                for (int j = 0; j < 8; j++) {
                    ra[j] = (aval && (k0 + glc + j) < K) ? Aptr[k0+j] : 0.f;
                    rb[j] = (bval && (k0 + glc + j) < K) ? Bptr[k0+j] : 0.f;
                }
            }
        }
        // compute on buffer cur: 2 k-atoms of 8
        #pragma unroll
        for (int ka = 0; ka < 2; ka++) {
            int kq = ka*8 + lr4;
            uint32_t af[4][4], bf[4][2];
            int mb = wm*64 + lq;
            #pragma unroll
            for (int i = 0; i < 4; i++) {
                af[i][0] = As[cur][kq    ][mb + i*16];
                af[i][1] = As[cur][kq    ][mb + i*16 + 8];
                af[i][2] = As[cur][kq + 4][mb + i*16];
                af[i][3] = As[cur][kq + 4][mb + i*16 + 8];
            }
            int nb = wn*32 + lq;
            #pragma unroll
            for (int j = 0; j < 4; j++) {
                bf[j][0] = Bs[cur][kq    ][nb + j*8];
                bf[j][1] = Bs[cur][kq + 4][nb + j*8];
            }
            #pragma unroll
            for (int i = 0; i < 4; i++)
                #pragma unroll
                for (int j = 0; j < 4; j++) {
                    asm volatile(
                        "mma.sync.aligned.m16n8k8.row.col.f32.tf32.tf32.f32 "
                        "{%0,%1,%2,%3}, {%4,%5,%6,%7}, {%8,%9}, {%0,%1,%2,%3};"
                        : "+f"(acc[i][j][0]), "+f"(acc[i][j][1]),
                          "+f"(acc[i][j][2]), "+f"(acc[i][j][3])
                        : "r"(af[i][0]), "r"(af[i][1]), "r"(af[i][2]), "r"(af[i][3]),
                          "r"(bf[j][0]), "r"(bf[j][1]));
                }
        }
        if (more) {
            #pragma unroll
            for (int j = 0; j < 8; j++) {
                As[cur^1][glc+j][glr] = to_tf32(ra[j]);
                Bs[cur^1][glc+j][glr] = to_tf32(rb[j]);
            }
        }
        __syncthreads();
    }

    // epilogue
    #pragma unroll
    for (int i = 0; i < 4; i++) {
        int row0 = bm + wm*64 + i*16 + lq;
        #pragma unroll
        for (int j = 0; j < 4; j++) {
            int col0 = bn + wn*32 + j*8 + lr4*2;
            #pragma unroll
            for (int half = 0; half < 2; half++) {
                int r = row0 + half*8;
                if (r >= M) continue;
                float* crow = C + (size_t)r * ldc;
                #pragma unroll
                for (int cc = 0; cc < 2; cc++) {
                    int n = col0 + cc;
                    if (n >= N) continue;
                    float v = acc[i][j][half*2 + cc];
                    if (EPI == 1) {
                        v += crow[n];
                    } else if (EPI == 2) {
                        v += bias[n];
                        v = (v > 20.f) ? v : log1pf(__expf(v));   // softplus
                    }
                    crow[n] = v;
                }
            }
        }
    }
}

// ---------------- selective scan: 16 lanes per (b,e), chunked prefetch ----------------
__global__ __launch_bounds__(256) void scan_kernel(
    const float* __restrict__ dt, const float* __restrict__ xin,
    const float* __restrict__ proj, const float* __restrict__ xz,
    const float* __restrict__ A_log, const float* __restrict__ Dp,
    float* __restrict__ y)
{
    int g = blockIdx.x * 16 + (threadIdx.x >> 4);  // group over (b,e)
    int n = threadIdx.x & 15;                      // state index
    int b = g / D_INNER;
    int e = g % D_INNER;
    float a  = -__expf(A_log[e * D_STATE + n]);
    float Dv = Dp[e];
    float h = 0.f;
    const float* dt_p = dt  + (size_t)b * SEQ * D_INNER + e;
    const float* x_p  = xin + (size_t)b * SEQ * D_INNER + e;
    const float* bc_p = proj + (size_t)b * SEQ * PROJ_DIM + DT_RANK + n;
    const float* z_p  = xz  + (size_t)b * SEQ * (2*D_INNER) + D_INNER + e;
    float* y_p        = y   + (size_t)b * SEQ * D_INNER + e;

    for (int l0 = 0; l0 < SEQ; l0 += 8) {
        float dtv[8], xv[8], Bv[8], Cv[8], zv[8];
        #pragma unroll
        for (int j = 0; j < 8; j++) {
            size_t l = (size_t)(l0 + j);
            dtv[j] = dt_p[l * D_INNER];
            xv[j]  = x_p [l * D_INNER];
            Bv[j]  = bc_p[l * PROJ_DIM];
            Cv[j]  = bc_p[l * PROJ_DIM + D_STATE];
            zv[j]  = z_p [l * (2*D_INNER)];
        }
        // precompute decay + drive so the serial chain is 8 pure FMAs
        float Ev[8], cv[8];
        #pragma unroll
        for (int j = 0; j < 8; j++) {
            Ev[j] = __expf(dtv[j] * a);
            cv[j] = dtv[j] * xv[j] * Bv[j];
        }
        #pragma unroll
        for (int j = 0; j < 8; j++) {
            h = fmaf(h, Ev[j], cv[j]);
            float yv = h * Cv[j];
            yv += __shfl_xor_sync(0xffffffffu, yv, 8);
            yv += __shfl_xor_sync(0xffffffffu, yv, 4);
            yv += __shfl_xor_sync(0xffffffffu, yv, 2);
            yv += __shfl_xor_sync(0xffffffffu, yv, 1);
            if (n == 0) {
                float z  = zv[j];
                float sz = z / (1.f + __expf(-z));          // silu(z)
                y_p[(size_t)(l0 + j) * D_INNER] = (yv + Dv * xv[j]) * sz;
            }
        }
    }
}

// ---------------- launcher ----------------
extern "C" void kernel_launch(void* const* d_in, const int* in_sizes, int n_in,
                              void* d_out, int out_size)
{
    const int*   tokens = (const int*)  d_in[0];
    const float* embed  = (const float*)d_in[1];
    const float* norm_w = (const float*)d_in[2];
    const float* in_w   = (const float*)d_in[3];
    const float* conv_w = (const float*)d_in[4];
    const float* conv_b = (const float*)d_in[5];
    const float* xp_w   = (const float*)d_in[6];
    const float* dt_w   = (const float*)d_in[7];
    const float* dt_b   = (const float*)d_in[8];
    const float* A_log  = (const float*)d_in[9];
    const float* Dp     = (const float*)d_in[10];
    const float* out_w  = (const float*)d_in[11];
    const float* fnorm  = (const float*)d_in[12];
    float* out = (float*)d_out;

    float *resid, *xnorm, *xz, *xin, *proj, *dtb, *yb;
    cudaGetSymbolAddress((void**)&resid, g_resid);
    cudaGetSymbolAddress((void**)&xnorm, g_xnorm);
    cudaGetSymbolAddress((void**)&xz,    g_xz);
    cudaGetSymbolAddress((void**)&xin,   g_xin);
    cudaGetSymbolAddress((void**)&proj,  g_proj);
    cudaGetSymbolAddress((void**)&dtb,   g_dt);
    cudaGetSymbolAddress((void**)&yb,    g_y);

    embed_kernel<<<NTOK, 128>>>(tokens, embed, resid);

    for (int i = 0; i < N_LAYER; i++) {
        rmsnorm_kernel<<<NTOK, 128>>>(resid, norm_w + (size_t)i * D_MODEL, xnorm);

        // xz = xnorm @ in_proj^T   (8192 x 1536 x 384)
        dim3 g1((2*D_INNER)/128, NTOK/128);
        tfgemm<0, true><<<g1, 256>>>(xnorm, D_MODEL,
                              in_w + (size_t)i * 2*D_INNER*D_MODEL, D_MODEL,
                              xz, 2*D_INNER, NTOK, 2*D_INNER, D_MODEL, nullptr);

        // conv + silu -> xin
        conv_silu_kernel<<<(NTOK*D_INNER + 255)/256, 256>>>(
            xz, conv_w + (size_t)i * D_INNER*D_CONV, conv_b + (size_t)i * D_INNER, xin);

        // proj = xin @ x_proj^T    (8192 x 56 x 768)
        dim3 g2(1, NTOK/128);
        tfgemm<0, true><<<g2, 256>>>(xin, D_INNER,
                             xp_w + (size_t)i * PROJ_DIM*D_INNER, D_INNER,
                             proj, PROJ_DIM, NTOK, PROJ_DIM, D_INNER, nullptr);

        // dt = softplus(proj[:, :24] @ dt_w^T + dt_b)   (8192 x 768 x 24)
        dim3 g3(D_INNER/128, NTOK/128);
        tfgemm<2, false><<<g3, 256>>>(proj, PROJ_DIM,
                              dt_w + (size_t)i * D_INNER*DT_RANK, DT_RANK,
                              dtb, D_INNER, NTOK, D_INNER, DT_RANK,
                              dt_b + (size_t)i * D_INNER);

        // selective scan + D skip + silu(z) gate -> yb
        scan_kernel<<<(BATCH*D_INNER)/16, 256>>>(
            dtb, xin, proj, xz,
            A_log + (size_t)i * D_INNER*D_STATE, Dp + (size_t)i * D_INNER, yb);

        // resid += yb @ out_proj^T  (8192 x 384 x 768)
        dim3 g4(D_MODEL/128, NTOK/128);
        tfgemm<1, true><<<g4, 256>>>(yb, D_INNER,
                              out_w + (size_t)i * D_MODEL*D_INNER, D_INNER,
                              resid, D_MODEL, NTOK, D_MODEL, D_INNER, nullptr);
    }

    rmsnorm_kernel<<<NTOK, 128>>>(resid, fnorm, xnorm);

    // logits = xnorm @ embed^T   (8192 x 5000 x 384)
    dim3 g5((VOCAB + 127)/128, NTOK/128);
    tfgemm<0, true><<<g5, 256>>>(xnorm, D_MODEL, embed, D_MODEL,
                          out, VOCAB, NTOK, VOCAB, D_MODEL, nullptr);
}

// round 7
// speedup vs baseline: 2.9141x; 1.0356x over previous
#include <cuda_runtime.h>
#include <cuda_fp16.h>
#include <math.h>
#include <stdint.h>

#define D_MODEL 384
#define N_LAYER 4
#define VOCAB   5000
#define D_INNER 768
#define D_STATE 16
#define DT_RANK 24
#define D_CONV  4
#define BATCH   4
#define SEQ     2048
#define NTOK    (BATCH*SEQ)                 // 8192
#define PROJ_DIM (DT_RANK + 2*D_STATE)      // 56

// ---------------- scratch (device globals; no runtime alloc) ----------------
__device__ float g_resid[NTOK*D_MODEL];
__device__ float g_xnorm[NTOK*D_MODEL];
__device__ float g_xz   [NTOK*2*D_INNER];
__device__ float g_xin  [NTOK*D_INNER];
__device__ float g_proj [NTOK*PROJ_DIM];
__device__ float g_dt   [NTOK*D_INNER];
__device__ float g_y    [NTOK*D_INNER];

// ---------------- helpers ----------------
__device__ __forceinline__ uint32_t smem_u32(const void* p) {
    uint32_t a;
    asm("{ .reg .u64 t; cvta.to.shared.u64 t, %1; cvt.u32.u64 %0, t; }" : "=r"(a) : "l"(p));
    return a;
}
__device__ __forceinline__ uint32_t pack2(float x, float y) {
    __half2 h = __floats2half2_rn(x, y);
    return *reinterpret_cast<uint32_t*>(&h);
}
__device__ __forceinline__ void ldmx4(uint32_t& r0, uint32_t& r1, uint32_t& r2, uint32_t& r3, uint32_t addr) {
    asm volatile("ldmatrix.sync.aligned.m8n8.x4.shared.b16 {%0,%1,%2,%3}, [%4];"
        : "=r"(r0), "=r"(r1), "=r"(r2), "=r"(r3) : "r"(addr));
}

// 16 consecutive fp32 -> 8 packed half2
template<bool FULLK>
__device__ __forceinline__ void load16h(const float* __restrict__ p, bool ok, int krem, uint32_t* h2) {
    if (FULLK) {
        if (ok) {
            #pragma unroll
            for (int j = 0; j < 4; j++) {
                float4 v = *(const float4*)(p + j*4);
                h2[j*2]   = pack2(v.x, v.y);
                h2[j*2+1] = pack2(v.z, v.w);
            }
        } else {
            #pragma unroll
            for (int j = 0; j < 8; j++) h2[j] = 0u;
        }
    } else {
        float t[16];
        #pragma unroll
        for (int j = 0; j < 16; j++) t[j] = (ok && j < krem) ? p[j] : 0.f;
        #pragma unroll
        for (int j = 0; j < 8; j++) h2[j] = pack2(t[2*j], t[2*j+1]);
    }
}

// ======== fp16 tensor GEMM: C[8192, N] = A[8192, K] * B[N, K]^T ========
// Block 128x128, k-tile 32, double-buffered smem (80B row pitch -> conflict-free
// ldmatrix), 8 warps (2m x 4n), warp tile 64x32, mma.m16n8k16 f16->f32.
// EPI: 0 store, 1 accumulate into C, 2 softplus(x + bias[n])
#define TILE_B   10240            // 128 rows * 80 B
#define BUF_B    (2*TILE_B)       // A tile + B tile per stage

template<int EPI, bool FULLK>
__global__ __launch_bounds__(256, 2) void hgemm(
    const float* __restrict__ A, int lda,
    const float* __restrict__ B, int ldb,
    float* __restrict__ C, int ldc,
    int N, int K, const float* __restrict__ bias)
{
    __shared__ __align__(16) uint8_t sm[2*BUF_B];
    int tid = threadIdx.x, lane = tid & 31, wid = tid >> 5;
    int bm = blockIdx.y * 128, bn = blockIdx.x * 128;
    int wm = wid >> 2, wn = wid & 3;
    int lq = lane >> 2, lr4 = lane & 3;

    // loader mapping: 128 rows x 32 k; thread -> (row, 16-k half)
    int row = tid & 127;
    int cb  = (tid >> 7) * 16;
    const float* Ar = A + (size_t)(bm + row) * lda + cb;
    const float* Br = B + (size_t)(bn + row) * ldb + cb;
    bool bok = (bn + row) < N;
    int ntiles = (K + 31) / 32;
    uint32_t stoff = (uint32_t)row * 80u + (uint32_t)cb * 2u;

    float acc[4][4][4];
    #pragma unroll
    for (int i = 0; i < 4; i++)
        #pragma unroll
        for (int j = 0; j < 4; j++)
            #pragma unroll
            for (int c = 0; c < 4; c++) acc[i][j][c] = 0.f;

    uint32_t pa[8], pb[8];
    load16h<FULLK>(Ar, true, K - cb, pa);
    load16h<FULLK>(Br, bok, K - cb, pb);

    // store tile 0
    {
        uint8_t* pA = sm + stoff;
        *(uint4*)pA        = make_uint4(pa[0], pa[1], pa[2], pa[3]);
        *(uint4*)(pA + 16) = make_uint4(pa[4], pa[5], pa[6], pa[7]);
        uint8_t* pB = sm + TILE_B + stoff;
        *(uint4*)pB        = make_uint4(pb[0], pb[1], pb[2], pb[3]);
        *(uint4*)(pB + 16) = make_uint4(pb[4], pb[5], pb[6], pb[7]);
    }
    __syncthreads();

    uint32_t sb = smem_u32(sm);
    // per-warp ldmatrix row offsets (constant across tiles)
    uint32_t a_row_off = (uint32_t)(wm*64 + (lane & 15)) * 80u + (uint32_t)(lane >> 4) * 16u;
    uint32_t b_row_off = (uint32_t)(wn*32 + (lane & 7) + ((lane >> 4) & 1) * 8) * 80u
                       + (uint32_t)((lane >> 3) & 1) * 16u;

    for (int t = 0; t < ntiles; t++) {
        int cur = t & 1;
        if (t + 1 < ntiles) {
            int k0 = (t + 1) * 32;
            load16h<FULLK>(Ar + k0, true, K - k0 - cb, pa);
            load16h<FULLK>(Br + k0, bok, K - k0 - cb, pb);
        }
        uint32_t smA = sb + cur * BUF_B;
        uint32_t smB = smA + TILE_B;
        #pragma unroll
        for (int kk = 0; kk < 2; kk++) {
            uint32_t af[4][4], bf[4][2];
            #pragma unroll
            for (int i = 0; i < 4; i++)
                ldmx4(af[i][0], af[i][1], af[i][2], af[i][3],
                      smA + a_row_off + (uint32_t)i * (16u*80u) + kk*32u);
            #pragma unroll
            for (int jp = 0; jp < 2; jp++)
                ldmx4(bf[jp*2][0], bf[jp*2][1], bf[jp*2+1][0], bf[jp*2+1][1],
                      smB + b_row_off + (uint32_t)jp * (16u*80u) + kk*32u);
            #pragma unroll
            for (int i = 0; i < 4; i++)
                #pragma unroll
                for (int j = 0; j < 4; j++) {
                    asm volatile(
                        "mma.sync.aligned.m16n8k16.row.col.f32.f16.f16.f32 "
                        "{%0,%1,%2,%3}, {%4,%5,%6,%7}, {%8,%9}, {%0,%1,%2,%3};"
                        : "+f"(acc[i][j][0]), "+f"(acc[i][j][1]),
                          "+f"(acc[i][j][2]), "+f"(acc[i][j][3])
                        : "r"(af[i][0]), "r"(af[i][1]), "r"(af[i][2]), "r"(af[i][3]),
                          "r"(bf[j][0]), "r"(bf[j][1]));
                }
        }
        if (t + 1 < ntiles) {
            uint8_t* pA = sm + (cur^1) * BUF_B + stoff;
            *(uint4*)pA        = make_uint4(pa[0], pa[1], pa[2], pa[3]);
            *(uint4*)(pA + 16) = make_uint4(pa[4], pa[5], pa[6], pa[7]);
            uint8_t* pB = sm + (cur^1) * BUF_B + TILE_B + stoff;
            *(uint4*)pB        = make_uint4(pb[0], pb[1], pb[2], pb[3]);
            *(uint4*)(pB + 16) = make_uint4(pb[4], pb[5], pb[6], pb[7]);
        }
        __syncthreads();
    }

    // epilogue (m16n8 accum layout)
    #pragma unroll
    for (int i = 0; i < 4; i++) {
        int row0 = bm + wm*64 + i*16 + lq;
        #pragma unroll
        for (int j = 0; j < 4; j++) {
            int col0 = bn + wn*32 + j*8 + lr4*2;
            #pragma unroll
            for (int half = 0; half < 2; half++) {
                int r = row0 + half*8;
                float* crow = C + (size_t)r * ldc;
                #pragma unroll
                for (int cc = 0; cc < 2; cc++) {
                    int n = col0 + cc;
                    if (n >= N) continue;
                    float v = acc[i][j][half*2 + cc];
                    if (EPI == 1) {
                        v += crow[n];
                    } else if (EPI == 2) {
                        v += bias[n];
                        v = (v > 20.f) ? v : log1pf(__expf(v));
                    }
                    crow[n] = v;
                }
            }
        }
    }
}

// ---------------- embedding gather ----------------
__global__ void embed_kernel(const int* __restrict__ tok,
                             const float* __restrict__ emb,
                             float* __restrict__ out)
{
    int row = blockIdx.x;
    int t = tok[row];
    const float* src = emb + (size_t)t * D_MODEL;
    float* dst = out + (size_t)row * D_MODEL;
    for (int i = threadIdx.x; i < D_MODEL; i += blockDim.x) dst[i] = src[i];
}

// ---------------- rmsnorm ----------------
__global__ void rmsnorm_kernel(const float* __restrict__ x,
                               const float* __restrict__ w,
                               float* __restrict__ out)
{
    int row = blockIdx.x;
    const float* xr = x + (size_t)row * D_MODEL;
    float v0 = xr[threadIdx.x];
    float v1 = xr[threadIdx.x + 128];
    float v2 = xr[threadIdx.x + 256];
    float s = v0*v0 + v1*v1 + v2*v2;
    #pragma unroll
    for (int o = 16; o; o >>= 1) s += __shfl_xor_sync(0xffffffffu, s, o);
    __shared__ float red[4];
    if ((threadIdx.x & 31) == 0) red[threadIdx.x >> 5] = s;
    __syncthreads();
    s = red[0] + red[1] + red[2] + red[3];
    float sc = rsqrtf(s * (1.0f / D_MODEL) + 1e-5f);
    float* orow = out + (size_t)row * D_MODEL;
    orow[threadIdx.x]       = v0 * sc * w[threadIdx.x];
    orow[threadIdx.x + 128] = v1 * sc * w[threadIdx.x + 128];
    orow[threadIdx.x + 256] = v2 * sc * w[threadIdx.x + 256];
}

// ---------------- causal depthwise conv (k=4) + SiLU ----------------
__global__ void conv_silu_kernel(const float* __restrict__ xz,
                                 const float* __restrict__ cw,
                                 const float* __restrict__ cb,
                                 float* __restrict__ out)
{
    int idx = blockIdx.x * blockDim.x + threadIdx.x;
    if (idx >= NTOK * D_INNER) return;
    int e = idx % D_INNER;
    int l = (idx / D_INNER) % SEQ;
    int b = idx / (D_INNER * SEQ);
    const float* base = xz + (size_t)b * SEQ * (2*D_INNER) + e;
    float acc = cb[e];
    #pragma unroll
    for (int j = 0; j < D_CONV; j++) {
        int lp = l - (D_CONV - 1) + j;
        if (lp >= 0)
            acc = fmaf(cw[e*D_CONV + j], base[(size_t)lp * (2*D_INNER)], acc);
    }
    out[idx] = acc / (1.f + __expf(-acc));
}

// ---------------- selective scan: 16 lanes per (b,e), chunked prefetch ----------------
__global__ __launch_bounds__(256) void scan_kernel(
    const float* __restrict__ dt, const float* __restrict__ xin,
    const float* __restrict__ proj, const float* __restrict__ xz,
    const float* __restrict__ A_log, const float* __restrict__ Dp,
    float* __restrict__ y)
{
    int g = blockIdx.x * 16 + (threadIdx.x >> 4);
    int n = threadIdx.x & 15;
    int b = g / D_INNER;
    int e = g % D_INNER;
    float a  = -__expf(A_log[e * D_STATE + n]);
    float Dv = Dp[e];
    float h = 0.f;
    const float* dt_p = dt  + (size_t)b * SEQ * D_INNER + e;
    const float* x_p  = xin + (size_t)b * SEQ * D_INNER + e;
    const float* bc_p = proj + (size_t)b * SEQ * PROJ_DIM + DT_RANK + n;
    const float* z_p  = xz  + (size_t)b * SEQ * (2*D_INNER) + D_INNER + e;
    float* y_p        = y   + (size_t)b * SEQ * D_INNER + e;

    for (int l0 = 0; l0 < SEQ; l0 += 8) {
        float dtv[8], xv[8], Bv[8], Cv[8], zv[8];
        #pragma unroll
        for (int j = 0; j < 8; j++) {
            size_t l = (size_t)(l0 + j);
            dtv[j] = dt_p[l * D_INNER];
            xv[j]  = x_p [l * D_INNER];
            Bv[j]  = bc_p[l * PROJ_DIM];
            Cv[j]  = bc_p[l * PROJ_DIM + D_STATE];
            zv[j]  = z_p [l * (2*D_INNER)];
        }
        float Ev[8], cv[8];
        #pragma unroll
        for (int j = 0; j < 8; j++) {
            Ev[j] = __expf(dtv[j] * a);
            cv[j] = dtv[j] * xv[j] * Bv[j];
        }
        #pragma unroll
        for (int j = 0; j < 8; j++) {
            h = fmaf(h, Ev[j], cv[j]);
            float yv = h * Cv[j];
            yv += __shfl_xor_sync(0xffffffffu, yv, 8);
            yv += __shfl_xor_sync(0xffffffffu, yv, 4);
            yv += __shfl_xor_sync(0xffffffffu, yv, 2);
            yv += __shfl_xor_sync(0xffffffffu, yv, 1);
            if (n == 0) {
                float z  = zv[j];
                float sz = z / (1.f + __expf(-z));
                y_p[(size_t)(l0 + j) * D_INNER] = (yv + Dv * xv[j]) * sz;
            }
        }
    }
}

// ---------------- launcher ----------------
extern "C" void kernel_launch(void* const* d_in, const int* in_sizes, int n_in,
                              void* d_out, int out_size)
{
    const int*   tokens = (const int*)  d_in[0];
    const float* embed  = (const float*)d_in[1];
    const float* norm_w = (const float*)d_in[2];
    const float* in_w   = (const float*)d_in[3];
    const float* conv_w = (const float*)d_in[4];
    const float* conv_b = (const float*)d_in[5];
    const float* xp_w   = (const float*)d_in[6];
    const float* dt_w   = (const float*)d_in[7];
    const float* dt_b   = (const float*)d_in[8];
    const float* A_log  = (const float*)d_in[9];
    const float* Dp     = (const float*)d_in[10];
    const float* out_w  = (const float*)d_in[11];
    const float* fnorm  = (const float*)d_in[12];
    float* out = (float*)d_out;

    float *resid, *xnorm, *xz, *xin, *proj, *dtb, *yb;
    cudaGetSymbolAddress((void**)&resid, g_resid);
    cudaGetSymbolAddress((void**)&xnorm, g_xnorm);
    cudaGetSymbolAddress((void**)&xz,    g_xz);
    cudaGetSymbolAddress((void**)&xin,   g_xin);
    cudaGetSymbolAddress((void**)&proj,  g_proj);
    cudaGetSymbolAddress((void**)&dtb,   g_dt);
    cudaGetSymbolAddress((void**)&yb,    g_y);

    embed_kernel<<<NTOK, 128>>>(tokens, embed, resid);

    const int MB = NTOK / 128;  // 64 row-blocks

    for (int i = 0; i < N_LAYER; i++) {
        rmsnorm_kernel<<<NTOK, 128>>>(resid, norm_w + (size_t)i * D_MODEL, xnorm);

        // xz = xnorm @ in_proj^T   (8192 x 1536 x 384)
        hgemm<0, true><<<dim3(1536/128, MB), 256>>>(
            xnorm, D_MODEL, in_w + (size_t)i * 2*D_INNER*D_MODEL, D_MODEL,
            xz, 2*D_INNER, 2*D_INNER, D_MODEL, nullptr);

        conv_silu_kernel<<<(NTOK*D_INNER + 255)/256, 256>>>(
            xz, conv_w + (size_t)i * D_INNER*D_CONV, conv_b + (size_t)i * D_INNER, xin);

        // proj = xin @ x_proj^T    (8192 x 56 x 768)
        hgemm<0, true><<<dim3(1, MB), 256>>>(
            xin, D_INNER, xp_w + (size_t)i * PROJ_DIM*D_INNER, D_INNER,
            proj, PROJ_DIM, PROJ_DIM, D_INNER, nullptr);

        // dt = softplus(proj[:, :24] @ dt_w^T + dt_b)   (8192 x 768 x 24)
        hgemm<2, false><<<dim3(768/128, MB), 256>>>(
            proj, PROJ_DIM, dt_w + (size_t)i * D_INNER*DT_RANK, DT_RANK,
            dtb, D_INNER, D_INNER, DT_RANK, dt_b + (size_t)i * D_INNER);

        scan_kernel<<<(BATCH*D_INNER)/16, 256>>>(
            dtb, xin, proj, xz,
            A_log + (size_t)i * D_INNER*D_STATE, Dp + (size_t)i * D_INNER, yb);

        // resid += yb @ out_proj^T  (8192 x 384 x 768)
        hgemm<1, true><<<dim3(384/128, MB), 256>>>(
            yb, D_INNER, out_w + (size_t)i * D_MODEL*D_INNER, D_INNER,
            resid, D_MODEL, D_MODEL, D_INNER, nullptr);
    }

    rmsnorm_kernel<<<NTOK, 128>>>(resid, fnorm, xnorm);

    // logits = xnorm @ embed^T   (8192 x 5000 x 384)
    hgemm<0, true><<<dim3((VOCAB + 127)/128, MB), 256>>>(
        xnorm, D_MODEL, embed, D_MODEL,
        out, VOCAB, VOCAB, D_MODEL, nullptr);
}

// round 8
// speedup vs baseline: 2.9150x; 1.0003x over previous
#include <cuda_runtime.h>
#include <cuda_fp16.h>
#include <math.h>
#include <stdint.h>

#define D_MODEL 384
#define N_LAYER 4
#define VOCAB   5000
#define D_INNER 768
#define D_STATE 16
#define DT_RANK 24
#define D_CONV  4
#define BATCH   4
#define SEQ     2048
#define NTOK    (BATCH*SEQ)                 // 8192
#define PROJ_DIM (DT_RANK + 2*D_STATE)      // 56

// ---------------- scratch (device globals; no runtime alloc) ----------------
__device__ float g_resid[NTOK*D_MODEL];
__device__ float g_xz   [NTOK*2*D_INNER];
__device__ float g_xin  [NTOK*D_INNER];
__device__ float g_proj [NTOK*PROJ_DIM];
__device__ float g_dt   [NTOK*D_INNER];

__device__ __half g_xnorm_h[NTOK*D_MODEL];
__device__ __half g_xin_h [NTOK*D_INNER];
__device__ __half g_proj_h[NTOK*PROJ_DIM];
__device__ __half g_y_h   [NTOK*D_INNER];
__device__ __half g_inw_h [N_LAYER*2*D_INNER*D_MODEL];
__device__ __half g_xpw_h [N_LAYER*PROJ_DIM*D_INNER];
__device__ __half g_dtw_h [N_LAYER*D_INNER*DT_RANK];
__device__ __half g_outw_h[N_LAYER*D_MODEL*D_INNER];
__device__ __half g_emb_h [VOCAB*D_MODEL];

// ---------------- helpers ----------------
__device__ __forceinline__ uint32_t smem_u32(const void* p) {
    uint32_t a;
    asm("{ .reg .u64 t; cvta.to.shared.u64 t, %1; cvt.u32.u64 %0, t; }" : "=r"(a) : "l"(p));
    return a;
}
__device__ __forceinline__ void ldmx4(uint32_t& r0, uint32_t& r1, uint32_t& r2, uint32_t& r3, uint32_t addr) {
    asm volatile("ldmatrix.sync.aligned.m8n8.x4.shared.b16 {%0,%1,%2,%3}, [%4];"
        : "=r"(r0), "=r"(r1), "=r"(r2), "=r"(r3) : "r"(addr));
}

// ---------------- fp32 -> fp16 conversion (weights, once per launch) ----------------
__global__ void f2h_kernel(const float* __restrict__ in, __half* __restrict__ out, int n)
{
    for (int i = blockIdx.x * blockDim.x + threadIdx.x; i < n; i += gridDim.x * blockDim.x)
        out[i] = __float2half_rn(in[i]);
}

// 16 consecutive halves loaded per thread (no conversion)
template<bool FULLK>
__device__ __forceinline__ void ld16h(const __half* __restrict__ p, bool ok, int krem, uint32_t* h2) {
    if (FULLK) {
        if (ok) {
            uint4 v0 = *(const uint4*)p;
            uint4 v1 = *(const uint4*)(p + 8);
            h2[0]=v0.x; h2[1]=v0.y; h2[2]=v0.z; h2[3]=v0.w;
            h2[4]=v1.x; h2[5]=v1.y; h2[6]=v1.z; h2[7]=v1.w;
        } else {
            #pragma unroll
            for (int j = 0; j < 8; j++) h2[j] = 0u;
        }
    } else {
        const unsigned short* u = (const unsigned short*)p;
        unsigned short t[16];
        #pragma unroll
        for (int j = 0; j < 16; j++) t[j] = (ok && j < krem) ? u[j] : (unsigned short)0;
        #pragma unroll
        for (int j = 0; j < 8; j++) h2[j] = (uint32_t)t[2*j] | ((uint32_t)t[2*j+1] << 16);
    }
}

// ======== fp16 tensor GEMM: C[8192, N] = A[8192, K] * B[N, K]^T (A,B fp16) ========
// Block 128x128, k-tile 32, double-buffered smem (80B pitch), 8 warps, m16n8k16.
// EPI: 0 store, 1 accumulate into C, 2 softplus(x + bias[n]).  WH: also write half copy.
#define TILE_B   10240            // 128 rows * 80 B
#define BUF_B    (2*TILE_B)

template<int EPI, bool FULLK, bool WH>
__global__ __launch_bounds__(256, 2) void hgemm(
    const __half* __restrict__ A, int lda,
    const __half* __restrict__ B, int ldb,
    float* __restrict__ C, int ldc, __half* __restrict__ Ch,
    int N, int K, const float* __restrict__ bias)
{
    __shared__ __align__(16) uint8_t sm[2*BUF_B];
    int tid = threadIdx.x, lane = tid & 31, wid = tid >> 5;
    int bm = blockIdx.y * 128, bn = blockIdx.x * 128;
    int wm = wid >> 2, wn = wid & 3;
    int lq = lane >> 2, lr4 = lane & 3;

    int row = tid & 127;
    int cb  = (tid >> 7) * 16;
    const __half* Ar = A + (size_t)(bm + row) * lda + cb;
    const __half* Br = B + (size_t)(bn + row) * ldb + cb;
    bool bok = (bn + row) < N;
    int ntiles = (K + 31) / 32;
    uint32_t stoff = (uint32_t)row * 80u + (uint32_t)cb * 2u;

    float acc[4][4][4];
    #pragma unroll
    for (int i = 0; i < 4; i++)
        #pragma unroll
        for (int j = 0; j < 4; j++)
            #pragma unroll
            for (int c = 0; c < 4; c++) acc[i][j][c] = 0.f;

    uint32_t pa[8], pb[8];
    ld16h<FULLK>(Ar, true, K - cb, pa);
    ld16h<FULLK>(Br, bok, K - cb, pb);
    {
        uint8_t* pA = sm + stoff;
        *(uint4*)pA        = make_uint4(pa[0], pa[1], pa[2], pa[3]);
        *(uint4*)(pA + 16) = make_uint4(pa[4], pa[5], pa[6], pa[7]);
        uint8_t* pB = sm + TILE_B + stoff;
        *(uint4*)pB        = make_uint4(pb[0], pb[1], pb[2], pb[3]);
        *(uint4*)(pB + 16) = make_uint4(pb[4], pb[5], pb[6], pb[7]);
    }
    __syncthreads();

    uint32_t sb = smem_u32(sm);
    uint32_t a_row_off = (uint32_t)(wm*64 + (lane & 15)) * 80u + (uint32_t)(lane >> 4) * 16u;
    uint32_t b_row_off = (uint32_t)(wn*32 + (lane & 7) + ((lane >> 4) & 1) * 8) * 80u
                       + (uint32_t)((lane >> 3) & 1) * 16u;

    for (int t = 0; t < ntiles; t++) {
        int cur = t & 1;
        if (t + 1 < ntiles) {
            int k0 = (t + 1) * 32;
            ld16h<FULLK>(Ar + k0, true, K - k0 - cb, pa);
            ld16h<FULLK>(Br + k0, bok, K - k0 - cb, pb);
        }
        uint32_t smA = sb + cur * BUF_B;
        uint32_t smB = smA + TILE_B;
        #pragma unroll
        for (int kk = 0; kk < 2; kk++) {
            uint32_t af[4][4], bf[4][2];
            #pragma unroll
            for (int i = 0; i < 4; i++)
                ldmx4(af[i][0], af[i][1], af[i][2], af[i][3],
                      smA + a_row_off + (uint32_t)i * (16u*80u) + kk*32u);
            #pragma unroll
            for (int jp = 0; jp < 2; jp++)
                ldmx4(bf[jp*2][0], bf[jp*2][1], bf[jp*2+1][0], bf[jp*2+1][1],
                      smB + b_row_off + (uint32_t)jp * (16u*80u) + kk*32u);
            #pragma unroll
            for (int i = 0; i < 4; i++)
                #pragma unroll
                for (int j = 0; j < 4; j++) {
                    asm volatile(
                        "mma.sync.aligned.m16n8k16.row.col.f32.f16.f16.f32 "
                        "{%0,%1,%2,%3}, {%4,%5,%6,%7}, {%8,%9}, {%0,%1,%2,%3};"
                        : "+f"(acc[i][j][0]), "+f"(acc[i][j][1]),
                          "+f"(acc[i][j][2]), "+f"(acc[i][j][3])
                        : "r"(af[i][0]), "r"(af[i][1]), "r"(af[i][2]), "r"(af[i][3]),
                          "r"(bf[j][0]), "r"(bf[j][1]));
                }
        }
        if (t + 1 < ntiles) {
            uint8_t* pA = sm + (cur^1) * BUF_B + stoff;
            *(uint4*)pA        = make_uint4(pa[0], pa[1], pa[2], pa[3]);
            *(uint4*)(pA + 16) = make_uint4(pa[4], pa[5], pa[6], pa[7]);
            uint8_t* pB = sm + (cur^1) * BUF_B + TILE_B + stoff;
            *(uint4*)pB        = make_uint4(pb[0], pb[1], pb[2], pb[3]);
            *(uint4*)(pB + 16) = make_uint4(pb[4], pb[5], pb[6], pb[7]);
        }
        __syncthreads();
    }

    #pragma unroll
    for (int i = 0; i < 4; i++) {
        int row0 = bm + wm*64 + i*16 + lq;
        #pragma unroll
        for (int j = 0; j < 4; j++) {
            int col0 = bn + wn*32 + j*8 + lr4*2;
            #pragma unroll
            for (int half = 0; half < 2; half++) {
                int r = row0 + half*8;
                float*  crow = C + (size_t)r * ldc;
                __half* hrow = WH ? (Ch + (size_t)r * ldc) : nullptr;
                #pragma unroll
                for (int cc = 0; cc < 2; cc++) {
                    int n = col0 + cc;
                    if (n >= N) continue;
                    float v = acc[i][j][half*2 + cc];
                    if (EPI == 1) {
                        v += crow[n];
                    } else if (EPI == 2) {
                        v += bias[n];
                        v = (v > 20.f) ? v : log1pf(__expf(v));
                    }
                    crow[n] = v;
                    if (WH) hrow[n] = __float2half_rn(v);
                }
            }
        }
    }
}

// ---------------- embedding gather ----------------
__global__ void embed_kernel(const int* __restrict__ tok,
                             const float* __restrict__ emb,
                             float* __restrict__ out)
{
    int row = blockIdx.x;
    int t = tok[row];
    const float* src = emb + (size_t)t * D_MODEL;
    float* dst = out + (size_t)row * D_MODEL;
    for (int i = threadIdx.x; i < D_MODEL; i += blockDim.x) dst[i] = src[i];
}

// ---------------- rmsnorm -> fp16 ----------------
__global__ void rmsnorm_kernel(const float* __restrict__ x,
                               const float* __restrict__ w,
                               __half* __restrict__ out)
{
    int row = blockIdx.x;
    const float* xr = x + (size_t)row * D_MODEL;
    float v0 = xr[threadIdx.x];
    float v1 = xr[threadIdx.x + 128];
    float v2 = xr[threadIdx.x + 256];
    float s = v0*v0 + v1*v1 + v2*v2;
    #pragma unroll
    for (int o = 16; o; o >>= 1) s += __shfl_xor_sync(0xffffffffu, s, o);
    __shared__ float red[4];
    if ((threadIdx.x & 31) == 0) red[threadIdx.x >> 5] = s;
    __syncthreads();
    s = red[0] + red[1] + red[2] + red[3];
    float sc = rsqrtf(s * (1.0f / D_MODEL) + 1e-5f);
    __half* orow = out + (size_t)row * D_MODEL;
    orow[threadIdx.x]       = __float2half_rn(v0 * sc * w[threadIdx.x]);
    orow[threadIdx.x + 128] = __float2half_rn(v1 * sc * w[threadIdx.x + 128]);
    orow[threadIdx.x + 256] = __float2half_rn(v2 * sc * w[threadIdx.x + 256]);
}

// ---------------- causal depthwise conv (k=4) + SiLU -> fp32 + fp16 ----------------
__global__ void conv_silu_kernel(const float* __restrict__ xz,
                                 const float* __restrict__ cw,
                                 const float* __restrict__ cb,
                                 float* __restrict__ out,
                                 __half* __restrict__ outh)
{
    int idx = blockIdx.x * blockDim.x + threadIdx.x;
    if (idx >= NTOK * D_INNER) return;
    int e = idx % D_INNER;
    int l = (idx / D_INNER) % SEQ;
    int b = idx / (D_INNER * SEQ);
    const float* base = xz + (size_t)b * SEQ * (2*D_INNER) + e;
    float acc = cb[e];
    #pragma unroll
    for (int j = 0; j < D_CONV; j++) {
        int lp = l - (D_CONV - 1) + j;
        if (lp >= 0)
            acc = fmaf(cw[e*D_CONV + j], base[(size_t)lp * (2*D_INNER)], acc);
    }
    float v = acc / (1.f + __expf(-acc));
    out[idx]  = v;
    outh[idx] = __float2half_rn(v);
}

// ---------------- selective scan: 16 lanes per (b,e); shuffles off the chain ----------------
__global__ __launch_bounds__(256) void scan_kernel(
    const float* __restrict__ dt, const float* __restrict__ xin,
    const float* __restrict__ proj, const float* __restrict__ xz,
    const float* __restrict__ A_log, const float* __restrict__ Dp,
    __half* __restrict__ y)
{
    int g = blockIdx.x * 16 + (threadIdx.x >> 4);
    int n = threadIdx.x & 15;
    int b = g / D_INNER;
    int e = g % D_INNER;
    float a  = -__expf(A_log[e * D_STATE + n]);
    float Dv = Dp[e];
    float h = 0.f;
    const float* dt_p = dt  + (size_t)b * SEQ * D_INNER + e;
    const float* x_p  = xin + (size_t)b * SEQ * D_INNER + e;
    const float* bc_p = proj + (size_t)b * SEQ * PROJ_DIM + DT_RANK + n;
    const float* z_p  = xz  + (size_t)b * SEQ * (2*D_INNER) + D_INNER + e;
    __half* y_p       = y   + (size_t)b * SEQ * D_INNER + e;

    for (int l0 = 0; l0 < SEQ; l0 += 8) {
        float dtv[8], xv[8], Bv[8], Cv[8], zv[8];
        #pragma unroll
        for (int j = 0; j < 8; j++) {
            size_t l = (size_t)(l0 + j);
            dtv[j] = dt_p[l * D_INNER];
            xv[j]  = x_p [l * D_INNER];
            Bv[j]  = bc_p[l * PROJ_DIM];
            Cv[j]  = bc_p[l * PROJ_DIM + D_STATE];
            zv[j]  = z_p [l * (2*D_INNER)];
        }
        float Ev[8], cv[8];
        #pragma unroll
        for (int j = 0; j < 8; j++) {
            Ev[j] = __expf(dtv[j] * a);
            cv[j] = dtv[j] * xv[j] * Bv[j];
        }
        float pr[8];
        #pragma unroll
        for (int j = 0; j < 8; j++) {        // serial chain: 1 FMA + 1 MUL per step
            h = fmaf(h, Ev[j], cv[j]);
            pr[j] = h * Cv[j];
        }
        #pragma unroll
        for (int j = 0; j < 8; j++) {        // reductions pipeline freely here
            float yv = pr[j];
            yv += __shfl_xor_sync(0xffffffffu, yv, 8);
            yv += __shfl_xor_sync(0xffffffffu, yv, 4);
            yv += __shfl_xor_sync(0xffffffffu, yv, 2);
            yv += __shfl_xor_sync(0xffffffffu, yv, 1);
            if (n == 0) {
                float z  = zv[j];
                float sz = z / (1.f + __expf(-z));
                y_p[(size_t)(l0 + j) * D_INNER] =
                    __float2half_rn((yv + Dv * xv[j]) * sz);
            }
        }
    }
}

// ---------------- launcher ----------------
extern "C" void kernel_launch(void* const* d_in, const int* in_sizes, int n_in,
                              void* d_out, int out_size)
{
    const int*   tokens = (const int*)  d_in[0];
    const float* embed  = (const float*)d_in[1];
    const float* norm_w = (const float*)d_in[2];
    const float* in_w   = (const float*)d_in[3];
    const float* conv_w = (const float*)d_in[4];
    const float* conv_b = (const float*)d_in[5];
    const float* xp_w   = (const float*)d_in[6];
    const float* dt_w   = (const float*)d_in[7];
    const float* dt_b   = (const float*)d_in[8];
    const float* A_log  = (const float*)d_in[9];
    const float* Dp     = (const float*)d_in[10];
    const float* out_w  = (const float*)d_in[11];
    const float* fnorm  = (const float*)d_in[12];
    float* out = (float*)d_out;

    float *resid, *xz, *xin, *proj, *dtb;
    __half *xnorm_h, *xin_h, *proj_h, *y_h, *inw_h, *xpw_h, *dtw_h, *outw_h, *emb_h;
    cudaGetSymbolAddress((void**)&resid,  g_resid);
    cudaGetSymbolAddress((void**)&xz,     g_xz);
    cudaGetSymbolAddress((void**)&xin,    g_xin);
    cudaGetSymbolAddress((void**)&proj,   g_proj);
    cudaGetSymbolAddress((void**)&dtb,    g_dt);
    cudaGetSymbolAddress((void**)&xnorm_h, g_xnorm_h);
    cudaGetSymbolAddress((void**)&xin_h,  g_xin_h);
    cudaGetSymbolAddress((void**)&proj_h, g_proj_h);
    cudaGetSymbolAddress((void**)&y_h,    g_y_h);
    cudaGetSymbolAddress((void**)&inw_h,  g_inw_h);
    cudaGetSymbolAddress((void**)&xpw_h,  g_xpw_h);
    cudaGetSymbolAddress((void**)&dtw_h,  g_dtw_h);
    cudaGetSymbolAddress((void**)&outw_h, g_outw_h);
    cudaGetSymbolAddress((void**)&emb_h,  g_emb_h);

    // weight conversions (graph nodes; cheap, deterministic)
    f2h_kernel<<<1024, 256>>>(in_w,  inw_h,  N_LAYER*2*D_INNER*D_MODEL);
    f2h_kernel<<<256,  256>>>(xp_w,  xpw_h,  N_LAYER*PROJ_DIM*D_INNER);
    f2h_kernel<<<128,  256>>>(dt_w,  dtw_h,  N_LAYER*D_INNER*DT_RANK);
    f2h_kernel<<<512,  256>>>(out_w, outw_h, N_LAYER*D_MODEL*D_INNER);
    f2h_kernel<<<1024, 256>>>(embed, emb_h,  VOCAB*D_MODEL);

    embed_kernel<<<NTOK, 128>>>(tokens, embed, resid);

    const int MB = NTOK / 128;  // 64 row-blocks

    for (int i = 0; i < N_LAYER; i++) {
        rmsnorm_kernel<<<NTOK, 128>>>(resid, norm_w + (size_t)i * D_MODEL, xnorm_h);

        // xz = xnorm @ in_proj^T   (8192 x 1536 x 384)
        hgemm<0, true, false><<<dim3(1536/128, MB), 256>>>(
            xnorm_h, D_MODEL, inw_h + (size_t)i * 2*D_INNER*D_MODEL, D_MODEL,
            xz, 2*D_INNER, nullptr, 2*D_INNER, D_MODEL, nullptr);

        conv_silu_kernel<<<(NTOK*D_INNER + 255)/256, 256>>>(
            xz, conv_w + (size_t)i * D_INNER*D_CONV, conv_b + (size_t)i * D_INNER,
            xin, xin_h);

        // proj = xin @ x_proj^T    (8192 x 56 x 768), fp32 + fp16 copies
        hgemm<0, true, true><<<dim3(1, MB), 256>>>(
            xin_h, D_INNER, xpw_h + (size_t)i * PROJ_DIM*D_INNER, D_INNER,
            proj, PROJ_DIM, proj_h, PROJ_DIM, D_INNER, nullptr);

        // dt = softplus(proj[:, :24] @ dt_w^T + dt_b)   (8192 x 768 x 24)
        hgemm<2, false, false><<<dim3(768/128, MB), 256>>>(
            proj_h, PROJ_DIM, dtw_h + (size_t)i * D_INNER*DT_RANK, DT_RANK,
            dtb, D_INNER, nullptr, D_INNER, DT_RANK, dt_b + (size_t)i * D_INNER);

        scan_kernel<<<(BATCH*D_INNER)/16, 256>>>(
            dtb, xin, proj, xz,
            A_log + (size_t)i * D_INNER*D_STATE, Dp + (size_t)i * D_INNER, y_h);

        // resid += y @ out_proj^T  (8192 x 384 x 768)
        hgemm<1, true, false><<<dim3(384/128, MB), 256>>>(
            y_h, D_INNER, outw_h + (size_t)i * D_MODEL*D_INNER, D_INNER,
            resid, D_MODEL, nullptr, D_MODEL, D_INNER, nullptr);
    }

    rmsnorm_kernel<<<NTOK, 128>>>(resid, fnorm, xnorm_h);

    // logits = xnorm @ embed^T   (8192 x 5000 x 384)
    hgemm<0, true, false><<<dim3((VOCAB + 127)/128, MB), 256>>>(
        xnorm_h, D_MODEL, emb_h, D_MODEL,
        out, VOCAB, nullptr, VOCAB, D_MODEL, nullptr);
}

// round 9
// speedup vs baseline: 2.9831x; 1.0234x over previous
#include <cuda_runtime.h>
#include <cuda_fp16.h>
#include <math.h>
#include <stdint.h>

#define D_MODEL 384
#define N_LAYER 4
#define VOCAB   5000
#define D_INNER 768
#define D_STATE 16
#define DT_RANK 24
#define D_CONV  4
#define BATCH   4
#define SEQ     2048
#define NTOK    (BATCH*SEQ)                 // 8192
#define PROJ_DIM (DT_RANK + 2*D_STATE)      // 56

// ---------------- scratch (device globals; no runtime alloc) ----------------
__device__ float g_resid[NTOK*D_MODEL];
__device__ float g_xz   [NTOK*2*D_INNER];
__device__ float g_xin  [NTOK*D_INNER];
__device__ float g_proj [NTOK*PROJ_DIM];
__device__ float g_dt   [NTOK*D_INNER];

__device__ __half g_xnorm_h[NTOK*D_MODEL];
__device__ __half g_xin_h [NTOK*D_INNER];
__device__ __half g_proj_h[NTOK*PROJ_DIM];
__device__ __half g_y_h   [NTOK*D_INNER];
__device__ __half g_inw_h [N_LAYER*2*D_INNER*D_MODEL];
__device__ __half g_xpw_h [N_LAYER*PROJ_DIM*D_INNER];
__device__ __half g_dtw_h [N_LAYER*D_INNER*DT_RANK];
__device__ __half g_outw_h[N_LAYER*D_MODEL*D_INNER];
__device__ __half g_emb_h [VOCAB*D_MODEL];

// ---------------- helpers ----------------
__device__ __forceinline__ uint32_t smem_u32(const void* p) {
    uint32_t a;
    asm("{ .reg .u64 t; cvta.to.shared.u64 t, %1; cvt.u32.u64 %0, t; }" : "=r"(a) : "l"(p));
    return a;
}
__device__ __forceinline__ void ldmx4(uint32_t& r0, uint32_t& r1, uint32_t& r2, uint32_t& r3, uint32_t addr) {
    asm volatile("ldmatrix.sync.aligned.m8n8.x4.shared.b16 {%0,%1,%2,%3}, [%4];"
        : "=r"(r0), "=r"(r1), "=r"(r2), "=r"(r3) : "r"(addr));
}
__device__ __forceinline__ void cpa16(uint32_t dst, const void* src, uint32_t srcsz) {
    asm volatile("cp.async.cg.shared.global [%0], [%1], 16, %2;"
        :: "r"(dst), "l"(src), "r"(srcsz) : "memory");
}
#define CP_COMMIT() asm volatile("cp.async.commit_group;" ::: "memory")
#define CP_WAIT2()  asm volatile("cp.async.wait_group 2;" ::: "memory")
#define CP_WAIT0()  asm volatile("cp.async.wait_group 0;" ::: "memory")

// ---------------- fp32 -> fp16 conversion (weights, once per launch) ----------------
__global__ void f2h_kernel(const float* __restrict__ in, __half* __restrict__ out, int n)
{
    for (int i = blockIdx.x * blockDim.x + threadIdx.x; i < n; i += gridDim.x * blockDim.x)
        out[i] = __float2half_rn(in[i]);
}

// ======== fp16 tensor GEMM: C[8192, N] = A[8192, K] * B[N, K]^T (A,B fp16) ========
// Block 128x128, k-tile 32, 4-stage cp.async pipeline, 80B smem pitch, 8 warps,
// mma.m16n8k16 f16->f32.  EPI: 0 store, 1 accumulate, 2 softplus(x+bias).
// WH: also write a half copy of C.
#define TILE_B   10240            // 128 rows * 80 B
#define STAGE_B  (2*TILE_B)       // A tile + B tile per stage
#define NSTAGE   4
#define HG_SMEM  (NSTAGE*STAGE_B) // 81920 B

template<int EPI, bool FULLK, bool WH>
__global__ __launch_bounds__(256, 2) void hgemm(
    const __half* __restrict__ A, int lda,
    const __half* __restrict__ B, int ldb,
    float* __restrict__ C, int ldc, __half* __restrict__ Ch,
    int N, int K, const float* __restrict__ bias)
{
    extern __shared__ __align__(16) uint8_t sm[];
    int tid = threadIdx.x, lane = tid & 31, wid = tid >> 5;
    int bm = blockIdx.y * 128, bn = blockIdx.x * 128;
    int wm = wid >> 2, wn = wid & 3;
    int lq = lane >> 2, lr4 = lane & 3;

    // loader mapping: thread -> (row 0..127, 16-half chunk-pair at cb)
    int row = tid & 127;
    int cb  = (tid >> 7) * 16;                 // 0 or 16 (halves)
    const __half* Ar = A + (size_t)(bm + row) * lda + cb;
    int brow = (bn + row) < N ? (bn + row) : 0;
    bool bok = (bn + row) < N;
    const __half* Br = B + (size_t)brow * ldb + cb;
    int ntiles = (K + 31) / 32;
    uint32_t sb = smem_u32(sm);
    uint32_t stoff = (uint32_t)row * 80u + (uint32_t)cb * 2u;

    float acc[4][4][4];
    #pragma unroll
    for (int i = 0; i < 4; i++)
        #pragma unroll
        for (int j = 0; j < 4; j++)
            #pragma unroll
            for (int c = 0; c < 4; c++) acc[i][j][c] = 0.f;

    // issue one stage's copies (stage index s -> slot s % NSTAGE)
    auto issue = [&](int s) {
        int slot = s & (NSTAGE - 1);
        int k0 = s * 32;
        uint32_t dA = sb + slot * STAGE_B + stoff;
        uint32_t dB = dA + TILE_B;
        #pragma unroll
        for (int c = 0; c < 2; c++) {
            int kh = k0 + cb + c * 8;          // first half index of this 16B chunk
            uint32_t szA, szB;
            if (FULLK) { szA = 16u; szB = bok ? 16u : 0u; }
            else {
                int rem = 2 * (K - kh);
                uint32_t sz = rem <= 0 ? 0u : (rem >= 16 ? 16u : (uint32_t)rem);
                szA = sz; szB = bok ? sz : 0u;
            }
            cpa16(dA + c*16u, Ar + k0 + c*8, szA);
            cpa16(dB + c*16u, Br + k0 + c*8, szB);
        }
    };

    // prologue: stages 0..NSTAGE-2 (empty commits past ntiles keep group order)
    #pragma unroll
    for (int s = 0; s < NSTAGE - 1; s++) {
        if (s < ntiles) issue(s);
        CP_COMMIT();
    }

    uint32_t a_row_off = (uint32_t)(wm*64 + (lane & 15)) * 80u + (uint32_t)(lane >> 4) * 16u;
    uint32_t b_row_off = (uint32_t)(wn*32 + (lane & 7) + ((lane >> 4) & 1) * 8) * 80u
                       + (uint32_t)((lane >> 3) & 1) * 16u;

    for (int t = 0; t < ntiles; t++) {
        int slot = t & (NSTAGE - 1);
        CP_WAIT2();
        __syncthreads();
        // issue stage t+NSTAGE-1 into the slot freed by iteration t-1
        if (t + NSTAGE - 1 < ntiles) issue(t + NSTAGE - 1);
        CP_COMMIT();

        uint32_t smA = sb + slot * STAGE_B;
        uint32_t smB = smA + TILE_B;
        #pragma unroll
        for (int kk = 0; kk < 2; kk++) {
            uint32_t af[4][4], bf[4][2];
            #pragma unroll
            for (int i = 0; i < 4; i++)
                ldmx4(af[i][0], af[i][1], af[i][2], af[i][3],
                      smA + a_row_off + (uint32_t)i * (16u*80u) + kk*32u);
            #pragma unroll
            for (int jp = 0; jp < 2; jp++)
                ldmx4(bf[jp*2][0], bf[jp*2][1], bf[jp*2+1][0], bf[jp*2+1][1],
                      smB + b_row_off + (uint32_t)jp * (16u*80u) + kk*32u);
            #pragma unroll
            for (int i = 0; i < 4; i++)
                #pragma unroll
                for (int j = 0; j < 4; j++) {
                    asm volatile(
                        "mma.sync.aligned.m16n8k16.row.col.f32.f16.f16.f32 "
                        "{%0,%1,%2,%3}, {%4,%5,%6,%7}, {%8,%9}, {%0,%1,%2,%3};"
                        : "+f"(acc[i][j][0]), "+f"(acc[i][j][1]),
                          "+f"(acc[i][j][2]), "+f"(acc[i][j][3])
                        : "r"(af[i][0]), "r"(af[i][1]), "r"(af[i][2]), "r"(af[i][3]),
                          "r"(bf[j][0]), "r"(bf[j][1]));
                }
        }
        __syncthreads();   // all warps done reading slot before it is refilled
    }
    CP_WAIT0();            // drain pending copies before exit

    #pragma unroll
    for (int i = 0; i < 4; i++) {
        int row0 = bm + wm*64 + i*16 + lq;
        #pragma unroll
        for (int j = 0; j < 4; j++) {
            int col0 = bn + wn*32 + j*8 + lr4*2;
            #pragma unroll
            for (int half = 0; half < 2; half++) {
                int r = row0 + half*8;
                float*  crow = C + (size_t)r * ldc;
                __half* hrow = WH ? (Ch + (size_t)r * ldc) : nullptr;
                #pragma unroll
                for (int cc = 0; cc < 2; cc++) {
                    int n = col0 + cc;
                    if (n >= N) continue;
                    float v = acc[i][j][half*2 + cc];
                    if (EPI == 1) {
                        v += crow[n];
                    } else if (EPI == 2) {
                        v += bias[n];
                        v = (v > 20.f) ? v : log1pf(__expf(v));
                    }
                    crow[n] = v;
                    if (WH) hrow[n] = __float2half_rn(v);
                }
            }
        }
    }
}

// ---------------- embedding gather ----------------
__global__ void embed_kernel(const int* __restrict__ tok,
                             const float* __restrict__ emb,
                             float* __restrict__ out)
{
    int row = blockIdx.x;
    int t = tok[row];
    const float* src = emb + (size_t)t * D_MODEL;
    float* dst = out + (size_t)row * D_MODEL;
    for (int i = threadIdx.x; i < D_MODEL; i += blockDim.x) dst[i] = src[i];
}

// ---------------- rmsnorm -> fp16 ----------------
__global__ void rmsnorm_kernel(const float* __restrict__ x,
                               const float* __restrict__ w,
                               __half* __restrict__ out)
{
    int row = blockIdx.x;
    const float* xr = x + (size_t)row * D_MODEL;
    float v0 = xr[threadIdx.x];
    float v1 = xr[threadIdx.x + 128];
    float v2 = xr[threadIdx.x + 256];
    float s = v0*v0 + v1*v1 + v2*v2;
    #pragma unroll
    for (int o = 16; o; o >>= 1) s += __shfl_xor_sync(0xffffffffu, s, o);
    __shared__ float red[4];
    if ((threadIdx.x & 31) == 0) red[threadIdx.x >> 5] = s;
    __syncthreads();
    s = red[0] + red[1] + red[2] + red[3];
    float sc = rsqrtf(s * (1.0f / D_MODEL) + 1e-5f);
    __half* orow = out + (size_t)row * D_MODEL;
    orow[threadIdx.x]       = __float2half_rn(v0 * sc * w[threadIdx.x]);
    orow[threadIdx.x + 128] = __float2half_rn(v1 * sc * w[threadIdx.x + 128]);
    orow[threadIdx.x + 256] = __float2half_rn(v2 * sc * w[threadIdx.x + 256]);
}

// ---------------- causal depthwise conv (k=4) + SiLU -> fp32 + fp16 ----------------
__global__ void conv_silu_kernel(const float* __restrict__ xz,
                                 const float* __restrict__ cw,
                                 const float* __restrict__ cb,
                                 float* __restrict__ out,
                                 __half* __restrict__ outh)
{
    int idx = blockIdx.x * blockDim.x + threadIdx.x;
    if (idx >= NTOK * D_INNER) return;
    int e = idx % D_INNER;
    int l = (idx / D_INNER) % SEQ;
    int b = idx / (D_INNER * SEQ);
    const float* base = xz + (size_t)b * SEQ * (2*D_INNER) + e;
    float acc = cb[e];
    #pragma unroll
    for (int j = 0; j < D_CONV; j++) {
        int lp = l - (D_CONV - 1) + j;
        if (lp >= 0)
            acc = fmaf(cw[e*D_CONV + j], base[(size_t)lp * (2*D_INNER)], acc);
    }
    float v = acc / (1.f + __expf(-acc));
    out[idx]  = v;
    outh[idx] = __float2half_rn(v);
}

// ---------------- selective scan ----------------
__global__ __launch_bounds__(256) void scan_kernel(
    const float* __restrict__ dt, const float* __restrict__ xin,
    const float* __restrict__ proj, const float* __restrict__ xz,
    const float* __restrict__ A_log, const float* __restrict__ Dp,
    __half* __restrict__ y)
{
    int g = blockIdx.x * 16 + (threadIdx.x >> 4);
    int n = threadIdx.x & 15;
    int b = g / D_INNER;
    int e = g % D_INNER;
    float a  = -__expf(A_log[e * D_STATE + n]);
    float Dv = Dp[e];
    float h = 0.f;
    const float* dt_p = dt  + (size_t)b * SEQ * D_INNER + e;
    const float* x_p  = xin + (size_t)b * SEQ * D_INNER + e;
    const float* bc_p = proj + (size_t)b * SEQ * PROJ_DIM + DT_RANK + n;
    const float* z_p  = xz  + (size_t)b * SEQ * (2*D_INNER) + D_INNER + e;
    __half* y_p       = y   + (size_t)b * SEQ * D_INNER + e;

    for (int l0 = 0; l0 < SEQ; l0 += 8) {
        float dtv[8], xv[8], Bv[8], Cv[8], zv[8];
        #pragma unroll
        for (int j = 0; j < 8; j++) {
            size_t l = (size_t)(l0 + j);
            dtv[j] = dt_p[l * D_INNER];
            xv[j]  = x_p [l * D_INNER];
            Bv[j]  = bc_p[l * PROJ_DIM];
            Cv[j]  = bc_p[l * PROJ_DIM + D_STATE];
            zv[j]  = z_p [l * (2*D_INNER)];
        }
        float Ev[8], cv[8];
        #pragma unroll
        for (int j = 0; j < 8; j++) {
            Ev[j] = __expf(dtv[j] * a);
            cv[j] = dtv[j] * xv[j] * Bv[j];
        }
        float pr[8];
        #pragma unroll
        for (int j = 0; j < 8; j++) {
            h = fmaf(h, Ev[j], cv[j]);
            pr[j] = h * Cv[j];
        }
        #pragma unroll
        for (int j = 0; j < 8; j++) {
            float yv = pr[j];
            yv += __shfl_xor_sync(0xffffffffu, yv, 8);
            yv += __shfl_xor_sync(0xffffffffu, yv, 4);
            yv += __shfl_xor_sync(0xffffffffu, yv, 2);
            yv += __shfl_xor_sync(0xffffffffu, yv, 1);
            if (n == 0) {
                float z  = zv[j];
                float sz = z / (1.f + __expf(-z));
                y_p[(size_t)(l0 + j) * D_INNER] =
                    __float2half_rn((yv + Dv * xv[j]) * sz);
            }
        }
    }
}

// ---------------- launcher ----------------
extern "C" void kernel_launch(void* const* d_in, const int* in_sizes, int n_in,
                              void* d_out, int out_size)
{
    const int*   tokens = (const int*)  d_in[0];
    const float* embed  = (const float*)d_in[1];
    const float* norm_w = (const float*)d_in[2];
    const float* in_w   = (const float*)d_in[3];
    const float* conv_w = (const float*)d_in[4];
    const float* conv_b = (const float*)d_in[5];
    const float* xp_w   = (const float*)d_in[6];
    const float* dt_w   = (const float*)d_in[7];
    const float* dt_b   = (const float*)d_in[8];
    const float* A_log  = (const float*)d_in[9];
    const float* Dp     = (const float*)d_in[10];
    const float* out_w  = (const float*)d_in[11];
    const float* fnorm  = (const float*)d_in[12];
    float* out = (float*)d_out;

    float *resid, *xz, *xin, *proj, *dtb;
    __half *xnorm_h, *xin_h, *proj_h, *y_h, *inw_h, *xpw_h, *dtw_h, *outw_h, *emb_h;
    cudaGetSymbolAddress((void**)&resid,  g_resid);
    cudaGetSymbolAddress((void**)&xz,     g_xz);
    cudaGetSymbolAddress((void**)&xin,    g_xin);
    cudaGetSymbolAddress((void**)&proj,   g_proj);
    cudaGetSymbolAddress((void**)&dtb,    g_dt);
    cudaGetSymbolAddress((void**)&xnorm_h, g_xnorm_h);
    cudaGetSymbolAddress((void**)&xin_h,  g_xin_h);
    cudaGetSymbolAddress((void**)&proj_h, g_proj_h);
    cudaGetSymbolAddress((void**)&y_h,    g_y_h);
    cudaGetSymbolAddress((void**)&inw_h,  g_inw_h);
    cudaGetSymbolAddress((void**)&xpw_h,  g_xpw_h);
    cudaGetSymbolAddress((void**)&dtw_h,  g_dtw_h);
    cudaGetSymbolAddress((void**)&outw_h, g_outw_h);
    cudaGetSymbolAddress((void**)&emb_h,  g_emb_h);

    // opt-in to 80KB dynamic smem for all hgemm instantiations (idempotent)
    cudaFuncSetAttribute(hgemm<0,true,false>, cudaFuncAttributeMaxDynamicSharedMemorySize, HG_SMEM);
    cudaFuncSetAttribute(hgemm<0,true,true>,  cudaFuncAttributeMaxDynamicSharedMemorySize, HG_SMEM);
    cudaFuncSetAttribute(hgemm<1,true,false>, cudaFuncAttributeMaxDynamicSharedMemorySize, HG_SMEM);
    cudaFuncSetAttribute(hgemm<2,false,false>,cudaFuncAttributeMaxDynamicSharedMemorySize, HG_SMEM);

    const int MB = NTOK / 128;  // 64 row-blocks

    // launch order arranged so launch #6 (ncu -s 5 -c 1) is the big in_proj hgemm
    embed_kernel<<<NTOK, 128>>>(tokens, embed, resid);                                   // 1
    rmsnorm_kernel<<<NTOK, 128>>>(resid, norm_w, xnorm_h);                               // 2
    f2h_kernel<<<1024, 256>>>(in_w,  inw_h,  N_LAYER*2*D_INNER*D_MODEL);                 // 3
    f2h_kernel<<<256,  256>>>(xp_w,  xpw_h,  N_LAYER*PROJ_DIM*D_INNER);                  // 4
    f2h_kernel<<<128,  256>>>(dt_w,  dtw_h,  N_LAYER*D_INNER*DT_RANK);                   // 5

    for (int i = 0; i < N_LAYER; i++) {
        if (i > 0)
            rmsnorm_kernel<<<NTOK, 128>>>(resid, norm_w + (size_t)i * D_MODEL, xnorm_h);

        // xz = xnorm @ in_proj^T   (8192 x 1536 x 384)     <- launch #6 when i==0
        hgemm<0, true, false><<<dim3(1536/128, MB), 256, HG_SMEM>>>(
            xnorm_h, D_MODEL, inw_h + (size_t)i * 2*D_INNER*D_MODEL, D_MODEL,
            xz, 2*D_INNER, nullptr, 2*D_INNER, D_MODEL, nullptr);

        if (i == 0) {
            f2h_kernel<<<512,  256>>>(out_w, outw_h, N_LAYER*D_MODEL*D_INNER);
            f2h_kernel<<<1024, 256>>>(embed, emb_h,  VOCAB*D_MODEL);
        }

        conv_silu_kernel<<<(NTOK*D_INNER + 255)/256, 256>>>(
            xz, conv_w + (size_t)i * D_INNER*D_CONV, conv_b + (size_t)i * D_INNER,
            xin, xin_h);

        // proj = xin @ x_proj^T    (8192 x 56 x 768), fp32 + fp16 copies
        hgemm<0, true, true><<<dim3(1, MB), 256, HG_SMEM>>>(
            xin_h, D_INNER, xpw_h + (size_t)i * PROJ_DIM*D_INNER, D_INNER,
            proj, PROJ_DIM, proj_h, PROJ_DIM, D_INNER, nullptr);

        // dt = softplus(proj[:, :24] @ dt_w^T + dt_b)   (8192 x 768 x 24)
        hgemm<2, false, false><<<dim3(768/128, MB), 256, HG_SMEM>>>(
            proj_h, PROJ_DIM, dtw_h + (size_t)i * D_INNER*DT_RANK, DT_RANK,
            dtb, D_INNER, nullptr, D_INNER, DT_RANK, dt_b + (size_t)i * D_INNER);

        scan_kernel<<<(BATCH*D_INNER)/16, 256>>>(
            dtb, xin, proj, xz,
            A_log + (size_t)i * D_INNER*D_STATE, Dp + (size_t)i * D_INNER, y_h);

        // resid += y @ out_proj^T  (8192 x 384 x 768)
        hgemm<1, true, false><<<dim3(384/128, MB), 256, HG_SMEM>>>(
            y_h, D_INNER, outw_h + (size_t)i * D_MODEL*D_INNER, D_INNER,
            resid, D_MODEL, nullptr, D_MODEL, D_INNER, nullptr);
    }

    rmsnorm_kernel<<<NTOK, 128>>>(resid, fnorm, xnorm_h);

    // logits = xnorm @ embed^T   (8192 x 5000 x 384)
    hgemm<0, true, false><<<dim3((VOCAB + 127)/128, MB), 256, HG_SMEM>>>(
        xnorm_h, D_MODEL, emb_h, D_MODEL,
        out, VOCAB, nullptr, VOCAB, D_MODEL, nullptr);
}